// round 11
// baseline (speedup 1.0000x reference)
#include <cuda_runtime.h>
#include <cuda_fp16.h>
#include <cstdint>

#define S_LEN  2048
#define BATCH  2
#define DMODEL 1024
#define NHEAD  16
#define DHEAD  64
#define NROWS  (S_LEN * BATCH)
#define BH     (BATCH * NHEAD)

// ---------------------------------------------------------------------------
// Static device scratch
// ---------------------------------------------------------------------------
__device__ __half g_Qh[(size_t)BH * S_LEN * DHEAD];   // [bh][s][d]
__device__ __half g_Kh[(size_t)BH * S_LEN * DHEAD];   // [bh][s][d]
__device__ __half g_Vt[(size_t)BH * DHEAD * S_LEN];   // [bh][d][s]
__device__ __half g_Xh[(size_t)NROWS * DMODEL];       // [token row][D]
__device__ __half g_Ph[(size_t)BH * S_LEN * S_LEN];   // unnormalized exp
__device__ float  g_Lp[(size_t)BH * 16 * S_LEN];      // row-sum partials
__device__ float  g_Li[(size_t)BH * S_LEN];           // 1 / rowsum

__device__ __forceinline__ unsigned pk(float x, float y) {
    __half2 h = __floats2half2_rn(x, y);
    return *(unsigned*)&h;
}

__device__ __forceinline__ void mma16(float d[4], const unsigned a[4], const unsigned b[2]) {
    asm volatile(
        "mma.sync.aligned.m16n8k16.row.col.f32.f16.f16.f32 "
        "{%0,%1,%2,%3},{%4,%5,%6,%7},{%8,%9},{%0,%1,%2,%3};"
        : "+f"(d[0]), "+f"(d[1]), "+f"(d[2]), "+f"(d[3])
        : "r"(a[0]), "r"(a[1]), "r"(a[2]), "r"(a[3]), "r"(b[0]), "r"(b[1]));
}

__device__ __forceinline__ unsigned saddr(const void* p) {
    return (unsigned)__cvta_generic_to_shared(p);
}

__device__ __forceinline__ void ldsm4(unsigned r[4], unsigned addr) {
    asm volatile("ldmatrix.sync.aligned.m8n8.x4.shared.b16 {%0,%1,%2,%3}, [%4];"
        : "=r"(r[0]), "=r"(r[1]), "=r"(r[2]), "=r"(r[3]) : "r"(addr));
}

__device__ __forceinline__ void ldsm2(unsigned r[2], unsigned addr) {
    asm volatile("ldmatrix.sync.aligned.m8n8.x2.shared.b16 {%0,%1}, [%2];"
        : "=r"(r[0]), "=r"(r[1]) : "r"(addr));
}

__device__ __forceinline__ void cp_async16(unsigned smem, const void* gptr) {
    asm volatile("cp.async.cg.shared.global [%0], [%1], 16;" :: "r"(smem), "l"(gptr));
}

// ---------------------------------------------------------------------------
// QKV projection: 128x128 tile, BK=32 halves, 8 warps (2x4), warp 64x32.
// mode: 0=Q, 1=K, 2=V(transposed output).
// ---------------------------------------------------------------------------
__global__ __launch_bounds__(256, 2) void proj_qkv_kernel(
    const float* __restrict__ A, const float* __restrict__ W,
    const float* __restrict__ bias, int mode)
{
    __shared__ unsigned As[128][20];
    __shared__ unsigned Bs[128][20];

    const int tid = threadIdx.x;
    const int m0 = blockIdx.y * 128;
    const int n0 = blockIdx.x * 128;
    const int lane = tid & 31;
    const int warp = tid >> 5;
    const int g = lane >> 2;
    const int t = lane & 3;
    const int wm = warp >> 2;
    const int wn = warp & 3;
    const int arow = ((lane >> 3) & 1) * 8 + (lane & 7);
    const int acol4 = (lane >> 4) * 4;
    const int brow = lane & 7;
    const int bcol4 = ((lane >> 3) & 1) * 4;

    float acc[4][4][4] = {};
    float4 pa[4], pw[4];

#pragma unroll
    for (int i = 0; i < 4; i++) {
        const int idx = tid + 256 * i;
        const int r = idx >> 3;
        const int c = idx & 7;
        pa[i] = *(const float4*)(A + (size_t)(m0 + r) * DMODEL + c * 4);
        pw[i] = *(const float4*)(W + (size_t)(n0 + r) * DMODEL + c * 4);
    }

    for (int k0 = 0; k0 < DMODEL; k0 += 32) {
        __syncthreads();
#pragma unroll
        for (int i = 0; i < 4; i++) {
            const int idx = tid + 256 * i;
            const int r = idx >> 3;
            const int c = idx & 7;
            As[r][c * 2] = pk(pa[i].x, pa[i].y);
            As[r][c * 2 + 1] = pk(pa[i].z, pa[i].w);
            Bs[r][c * 2] = pk(pw[i].x, pw[i].y);
            Bs[r][c * 2 + 1] = pk(pw[i].z, pw[i].w);
        }
        __syncthreads();
        if (k0 + 32 < DMODEL) {
#pragma unroll
            for (int i = 0; i < 4; i++) {
                const int idx = tid + 256 * i;
                const int r = idx >> 3;
                const int c = idx & 7;
                pa[i] = *(const float4*)(A + (size_t)(m0 + r) * DMODEL + k0 + 32 + c * 4);
                pw[i] = *(const float4*)(W + (size_t)(n0 + r) * DMODEL + k0 + 32 + c * 4);
            }
        }
#pragma unroll
        for (int ks = 0; ks < 2; ks++) {
            const int kw = ks * 8;
            unsigned af[4][4], bf[4][2];
#pragma unroll
            for (int mt = 0; mt < 4; mt++)
                ldsm4(af[mt], saddr(&As[wm * 64 + mt * 16 + arow][kw + acol4]));
#pragma unroll
            for (int nt = 0; nt < 4; nt++)
                ldsm2(bf[nt], saddr(&Bs[wn * 32 + nt * 8 + brow][kw + bcol4]));
#pragma unroll
            for (int mt = 0; mt < 4; mt++)
#pragma unroll
                for (int nt = 0; nt < 4; nt++)
                    mma16(acc[mt][nt], af[mt], bf[nt]);
        }
    }

    __half* dstQ = (mode == 0) ? g_Qh : g_Kh;

#pragma unroll
    for (int nt = 0; nt < 4; nt++) {
        const int n = n0 + wn * 32 + nt * 8 + 2 * t;
        const float2 bb = *(const float2*)(bias + n);
        const int h = n >> 6;
        const int d = n & 63;
#pragma unroll
        for (int mt = 0; mt < 4; mt++) {
            const int mlo = m0 + wm * 64 + mt * 16 + g;
            const int s0 = mlo >> 1, b0 = mlo & 1;
            const int s1 = s0 + 4;
            const int bh = b0 * NHEAD + h;
            float v00 = acc[mt][nt][0] + bb.x;
            float v01 = acc[mt][nt][1] + bb.y;
            float v10 = acc[mt][nt][2] + bb.x;
            float v11 = acc[mt][nt][3] + bb.y;
            if (mode != 2) {
                *(__half2*)(dstQ + ((size_t)bh * S_LEN + s0) * DHEAD + d) = __floats2half2_rn(v00, v01);
                *(__half2*)(dstQ + ((size_t)bh * S_LEN + s1) * DHEAD + d) = __floats2half2_rn(v10, v11);
            } else {
                __half* base = g_Vt + (size_t)bh * DHEAD * S_LEN;
                base[(size_t)d * S_LEN + s0] = __float2half_rn(v00);
                base[(size_t)(d + 1) * S_LEN + s0] = __float2half_rn(v01);
                base[(size_t)d * S_LEN + s1] = __float2half_rn(v10);
                base[(size_t)(d + 1) * S_LEN + s1] = __float2half_rn(v11);
            }
        }
    }
}

// ---------------------------------------------------------------------------
// Output projection: out = Xh(fp16) @ Wo^T + bo, fp32 out.
// ---------------------------------------------------------------------------
__global__ __launch_bounds__(256, 2) void proj_o_kernel(
    const float* __restrict__ W, const float* __restrict__ bias,
    float* __restrict__ C)
{
    __shared__ unsigned As[128][20];
    __shared__ unsigned Bs[128][20];

    const int tid = threadIdx.x;
    const int m0 = blockIdx.y * 128;
    const int n0 = blockIdx.x * 128;
    const int lane = tid & 31;
    const int warp = tid >> 5;
    const int g = lane >> 2;
    const int t = lane & 3;
    const int wm = warp >> 2;
    const int wn = warp & 3;
    const int arow = ((lane >> 3) & 1) * 8 + (lane & 7);
    const int acol4 = (lane >> 4) * 4;
    const int brow = lane & 7;
    const int bcol4 = ((lane >> 3) & 1) * 4;

    float acc[4][4][4] = {};
    uint4 pa[2];
    float4 pw[4];

#pragma unroll
    for (int i = 0; i < 2; i++) {
        const int idx = tid + 256 * i;
        const int r = idx >> 2;
        const int c = idx & 3;
        pa[i] = *(const uint4*)(g_Xh + (size_t)(m0 + r) * DMODEL + c * 8);
    }
#pragma unroll
    for (int i = 0; i < 4; i++) {
        const int idx = tid + 256 * i;
        const int r = idx >> 3;
        const int c = idx & 7;
        pw[i] = *(const float4*)(W + (size_t)(n0 + r) * DMODEL + c * 4);
    }

    for (int k0 = 0; k0 < DMODEL; k0 += 32) {
        __syncthreads();
#pragma unroll
        for (int i = 0; i < 2; i++) {
            const int idx = tid + 256 * i;
            const int r = idx >> 2;
            const int c = idx & 3;
            *(uint4*)&As[r][c * 4] = pa[i];
        }
#pragma unroll
        for (int i = 0; i < 4; i++) {
            const int idx = tid + 256 * i;
            const int r = idx >> 3;
            const int c = idx & 7;
            Bs[r][c * 2] = pk(pw[i].x, pw[i].y);
            Bs[r][c * 2 + 1] = pk(pw[i].z, pw[i].w);
        }
        __syncthreads();
        if (k0 + 32 < DMODEL) {
#pragma unroll
            for (int i = 0; i < 2; i++) {
                const int idx = tid + 256 * i;
                const int r = idx >> 2;
                const int c = idx & 3;
                pa[i] = *(const uint4*)(g_Xh + (size_t)(m0 + r) * DMODEL + k0 + 32 + c * 8);
            }
#pragma unroll
            for (int i = 0; i < 4; i++) {
                const int idx = tid + 256 * i;
                const int r = idx >> 3;
                const int c = idx & 7;
                pw[i] = *(const float4*)(W + (size_t)(n0 + r) * DMODEL + k0 + 32 + c * 4);
            }
        }
#pragma unroll
        for (int ks = 0; ks < 2; ks++) {
            const int kw = ks * 8;
            unsigned af[4][4], bf[4][2];
#pragma unroll
            for (int mt = 0; mt < 4; mt++)
                ldsm4(af[mt], saddr(&As[wm * 64 + mt * 16 + arow][kw + acol4]));
#pragma unroll
            for (int nt = 0; nt < 4; nt++)
                ldsm2(bf[nt], saddr(&Bs[wn * 32 + nt * 8 + brow][kw + bcol4]));
#pragma unroll
            for (int mt = 0; mt < 4; mt++)
#pragma unroll
                for (int nt = 0; nt < 4; nt++)
                    mma16(acc[mt][nt], af[mt], bf[nt]);
        }
    }

#pragma unroll
    for (int nt = 0; nt < 4; nt++) {
        const int col = n0 + wn * 32 + nt * 8 + 2 * t;
        const float2 bb = *(const float2*)(bias + col);
#pragma unroll
        for (int mt = 0; mt < 4; mt++) {
            const int mlo = m0 + wm * 64 + mt * 16 + g;
            float2 o0 = {acc[mt][nt][0] + bb.x, acc[mt][nt][1] + bb.y};
            float2 o1 = {acc[mt][nt][2] + bb.x, acc[mt][nt][3] + bb.y};
            *(float2*)(C + (size_t)mlo * DMODEL + col) = o0;
            *(float2*)(C + (size_t)(mlo + 8) * DMODEL + col) = o1;
        }
    }
}

// ---------------------------------------------------------------------------
// Scores + exp: p_u = exp(qk/8 + mask - 4) (fp16) + row-sum partials.
// Mask tile staged in smem via cp.async (overlaps with MMA); P tile staged
// in smem (aliasing Q/K tiles), then coalesced copy-out.
// Dynamic smem: Tile 36864 + redL 2048 + Ms 67584 = 106496 bytes.
// ---------------------------------------------------------------------------
#define SC_TILE  0
#define SC_REDL  36864
#define SC_MS    38912
#define SC_TOTAL 106496

__global__ __launch_bounds__(256) void scores_exp_kernel(const float* __restrict__ mask)
{
    extern __shared__ char dsm[];
    unsigned (*As)[36] = (unsigned(*)[36])(dsm + SC_TILE);            // 128x36
    unsigned (*Bs)[36] = (unsigned(*)[36])(dsm + SC_TILE + 18432);    // 128x36
    float (*redL)[128] = (float(*)[128])(dsm + SC_REDL);
    float* Ms          = (float*)(dsm + SC_MS);                       // 128 x pitch132 fp32
    unsigned* Pst      = (unsigned*)(dsm + SC_TILE);                  // P stage: 128 x pitch68

    const int tid = threadIdx.x;
    const int bh = blockIdx.z;
    const int b = bh >> 4;
    const int sq0 = blockIdx.y * 128;
    const int st0 = blockIdx.x * 128;
    const int lane = tid & 31;
    const int warp = tid >> 5;
    const int g = lane >> 2;
    const int t = lane & 3;
    const int wm = warp >> 2;
    const int wn = warp & 3;
    const int arow = ((lane >> 3) & 1) * 8 + (lane & 7);
    const int acol4 = (lane >> 4) * 4;
    const int brow = lane & 7;
    const int bcol4 = ((lane >> 3) & 1) * 4;

    const __half* Qh = g_Qh + (size_t)bh * S_LEN * DHEAD;
    const __half* Kh = g_Kh + (size_t)bh * S_LEN * DHEAD;

    // kick off mask tile -> smem via cp.async (fully coalesced, 16B ops)
#pragma unroll
    for (int i = 0; i < 16; i++) {
        const int idx = tid + 256 * i;       // 0..4095
        const int r = idx >> 5;              // 0..127
        const int c = idx & 31;              // float4 index in row
        cp_async16(saddr(&Ms[(size_t)r * 132 + c * 4]),
                   mask + ((size_t)b * S_LEN + sq0 + r) * S_LEN + st0 + c * 4);
    }
    asm volatile("cp.async.commit_group;");

#pragma unroll
    for (int i = 0; i < 4; i++) {
        const int idx = tid + 256 * i;
        const int r = idx >> 3;
        const int c = idx & 7;
        *(uint4*)&As[r][c * 4] = *(const uint4*)(Qh + (size_t)(sq0 + r) * DHEAD + c * 8);
        *(uint4*)&Bs[r][c * 4] = *(const uint4*)(Kh + (size_t)(st0 + r) * DHEAD + c * 8);
    }
    __syncthreads();

    float acc[4][4][4] = {};
#pragma unroll
    for (int ks = 0; ks < 4; ks++) {
        const int kw = ks * 8;
        unsigned af[4][4], bf[4][2];
#pragma unroll
        for (int mt = 0; mt < 4; mt++)
            ldsm4(af[mt], saddr(&As[wm * 64 + mt * 16 + arow][kw + acol4]));
#pragma unroll
        for (int nt = 0; nt < 4; nt++)
            ldsm2(bf[nt], saddr(&Bs[wn * 32 + nt * 8 + brow][kw + bcol4]));
#pragma unroll
        for (int mt = 0; mt < 4; mt++)
#pragma unroll
            for (int nt = 0; nt < 4; nt++)
                mma16(acc[mt][nt], af[mt], bf[nt]);
    }

    asm volatile("cp.async.wait_group 0;");
    __syncthreads();   // fragment reads done (Tile reusable) + mask visible to all

    const float scale = 0.125f;
#pragma unroll
    for (int mt = 0; mt < 4; mt++) {
        const int r_lo = wm * 64 + mt * 16 + g;
        float rs0 = 0.f, rs1 = 0.f;
#pragma unroll
        for (int nt = 0; nt < 4; nt++) {
            const int cc = wn * 32 + nt * 8 + 2 * t;
            float2 mk0 = *(const float2*)&Ms[(size_t)r_lo * 132 + cc];
            float2 mk1 = *(const float2*)&Ms[(size_t)(r_lo + 8) * 132 + cc];
            float p00 = __expf(acc[mt][nt][0] * scale + mk0.x - 4.0f);
            float p01 = __expf(acc[mt][nt][1] * scale + mk0.y - 4.0f);
            float p10 = __expf(acc[mt][nt][2] * scale + mk1.x - 4.0f);
            float p11 = __expf(acc[mt][nt][3] * scale + mk1.y - 4.0f);
            const int wcol = wn * 16 + nt * 4 + t;      // word col within 64-word row
            Pst[(size_t)r_lo * 68 + wcol] = pk(p00, p01);
            Pst[(size_t)(r_lo + 8) * 68 + wcol] = pk(p10, p11);
            rs0 += p00 + p01;
            rs1 += p10 + p11;
        }
        rs0 += __shfl_xor_sync(0xffffffffu, rs0, 1);
        rs0 += __shfl_xor_sync(0xffffffffu, rs0, 2);
        rs1 += __shfl_xor_sync(0xffffffffu, rs1, 1);
        rs1 += __shfl_xor_sync(0xffffffffu, rs1, 2);
        if (t == 0) {
            redL[wn][r_lo] = rs0;
            redL[wn][r_lo + 8] = rs1;
        }
    }
    __syncthreads();

    // coalesced copy-out: 128 rows x 16 uint4 (256B) per row
#pragma unroll
    for (int i = 0; i < 8; i++) {
        const int idx = tid + 256 * i;       // 0..2047
        const int r = idx >> 4;
        const int j = idx & 15;
        uint4 v = *(const uint4*)&Pst[(size_t)r * 68 + j * 4];
        *(uint4*)(g_Ph + ((size_t)bh * S_LEN + sq0 + r) * S_LEN + st0 + j * 8) = v;
    }

    if (tid < 128) {
        float s = redL[0][tid] + redL[1][tid] + redL[2][tid] + redL[3][tid];
        g_Lp[((size_t)bh * 16 + blockIdx.x) * S_LEN + sq0 + tid] = s;
    }
}

// ---------------------------------------------------------------------------
// Deterministic reduce of row-sum partials -> 1/l
// ---------------------------------------------------------------------------
__global__ __launch_bounds__(256) void sumL_kernel()
{
    const int idx = blockIdx.x * 256 + threadIdx.x;
    const int bh = idx >> 11;
    const int s = idx & 2047;
    float acc = 0.f;
#pragma unroll
    for (int j = 0; j < 16; j++)
        acc += g_Lp[((size_t)bh * 16 + j) * S_LEN + s];
    g_Li[idx] = 1.0f / acc;
}

// ---------------------------------------------------------------------------
// PV: Xh = (P_u @ V) * (1/l). 128x64 tile, BK=32, double-buffered.
// ---------------------------------------------------------------------------
__global__ __launch_bounds__(256, 2) void pv_kernel()
{
    __shared__ unsigned Ps[2][128][20];
    __shared__ unsigned Vs[2][64][20];

    const int tid = threadIdx.x;
    const int bh = blockIdx.y;
    const int b = bh >> 4;
    const int h = bh & 15;
    const int m0 = blockIdx.x * 128;
    const int lane = tid & 31;
    const int warp = tid >> 5;
    const int g = lane >> 2;
    const int t = lane & 3;
    const int wm = warp >> 1;
    const int wn = warp & 1;
    const int arow = ((lane >> 3) & 1) * 8 + (lane & 7);
    const int acol4 = (lane >> 4) * 4;
    const int brow = lane & 7;
    const int bcol4 = ((lane >> 3) & 1) * 4;

    const __half* Ph = g_Ph + (size_t)bh * S_LEN * S_LEN;
    const __half* Vt = g_Vt + (size_t)bh * DHEAD * S_LEN;

    float acc[2][4][4] = {};
    uint4 pp[2], vv;

#pragma unroll
    for (int i = 0; i < 2; i++) {
        const int idx = tid + 256 * i;
        pp[i] = *(const uint4*)(Ph + (size_t)(m0 + (idx >> 2)) * S_LEN + (idx & 3) * 8);
    }
    vv = *(const uint4*)(Vt + (size_t)(tid >> 2) * S_LEN + (tid & 3) * 8);
#pragma unroll
    for (int i = 0; i < 2; i++) {
        const int idx = tid + 256 * i;
        *(uint4*)&Ps[0][idx >> 2][(idx & 3) * 4] = pp[i];
    }
    *(uint4*)&Vs[0][tid >> 2][(tid & 3) * 4] = vv;
    __syncthreads();

    for (int it = 0; it < S_LEN / 32; it++) {
        const int cur = it & 1;
        const int k1 = (it + 1) * 32;
        if (k1 < S_LEN) {
#pragma unroll
            for (int i = 0; i < 2; i++) {
                const int idx = tid + 256 * i;
                pp[i] = *(const uint4*)(Ph + (size_t)(m0 + (idx >> 2)) * S_LEN + k1 + (idx & 3) * 8);
            }
            vv = *(const uint4*)(Vt + (size_t)(tid >> 2) * S_LEN + k1 + (tid & 3) * 8);
        }
#pragma unroll
        for (int ks = 0; ks < 2; ks++) {
            const int kw = ks * 8;
            unsigned af[2][4], bf[4][2];
#pragma unroll
            for (int mt = 0; mt < 2; mt++)
                ldsm4(af[mt], saddr(&Ps[cur][wm * 32 + mt * 16 + arow][kw + acol4]));
#pragma unroll
            for (int nt = 0; nt < 4; nt++)
                ldsm2(bf[nt], saddr(&Vs[cur][wn * 32 + nt * 8 + brow][kw + bcol4]));
#pragma unroll
            for (int mt = 0; mt < 2; mt++)
#pragma unroll
                for (int nt = 0; nt < 4; nt++)
                    mma16(acc[mt][nt], af[mt], bf[nt]);
        }
        if (k1 < S_LEN) {
#pragma unroll
            for (int i = 0; i < 2; i++) {
                const int idx = tid + 256 * i;
                *(uint4*)&Ps[cur ^ 1][idx >> 2][(idx & 3) * 4] = pp[i];
            }
            *(uint4*)&Vs[cur ^ 1][tid >> 2][(tid & 3) * 4] = vv;
        }
        __syncthreads();
    }

#pragma unroll
    for (int mt = 0; mt < 2; mt++) {
        const int mlo = m0 + wm * 32 + mt * 16 + g;
        const float inv0 = g_Li[(size_t)bh * S_LEN + mlo];
        const float inv1 = g_Li[(size_t)bh * S_LEN + mlo + 8];
#pragma unroll
        for (int nt = 0; nt < 4; nt++) {
            const int col = wn * 32 + nt * 8 + 2 * t;
            *(__half2*)(g_Xh + ((size_t)(mlo * BATCH + b)) * DMODEL + h * DHEAD + col) =
                __floats2half2_rn(acc[mt][nt][0] * inv0, acc[mt][nt][1] * inv0);
            *(__half2*)(g_Xh + ((size_t)((mlo + 8) * BATCH + b)) * DMODEL + h * DHEAD + col) =
                __floats2half2_rn(acc[mt][nt][2] * inv1, acc[mt][nt][3] * inv1);
        }
    }
}

// ---------------------------------------------------------------------------
// attn[b][s][t] = sum_h p_u * (1/l) / 16
// ---------------------------------------------------------------------------
__global__ __launch_bounds__(256) void mean_kernel(float* __restrict__ attn)
{
    const int s = blockIdx.x;
    const int b = blockIdx.y;
    const int tid = threadIdx.x;

    float acc[8] = {};
#pragma unroll
    for (int h = 0; h < NHEAD; h++) {
        const int bh = b * NHEAD + h;
        const float inv = g_Li[(size_t)bh * S_LEN + s];
        uint4 u = *(const uint4*)(g_Ph + ((size_t)bh * S_LEN + s) * S_LEN + tid * 8);
        const __half2* hp = (const __half2*)&u;
#pragma unroll
        for (int j = 0; j < 4; j++) {
            float2 f = __half22float2(hp[j]);
            acc[2 * j] += f.x * inv;
            acc[2 * j + 1] += f.y * inv;
        }
    }
    const float im = 1.0f / NHEAD;
    float4 o0 = {acc[0] * im, acc[1] * im, acc[2] * im, acc[3] * im};
    float4 o1 = {acc[4] * im, acc[5] * im, acc[6] * im, acc[7] * im};
    float* dst = attn + ((size_t)b * S_LEN + s) * S_LEN + tid * 8;
    *(float4*)dst = o0;
    *(float4*)(dst + 4) = o1;
}

// ---------------------------------------------------------------------------
// Launch
// ---------------------------------------------------------------------------
extern "C" void kernel_launch(void* const* d_in, const int* in_sizes, int n_in,
                              void* d_out, int out_size)
{
    (void)in_sizes; (void)n_in; (void)out_size;

    const float* query = (const float*)d_in[0];
    const float* key_in = (const float*)d_in[1];
    const float* value = (const float*)d_in[2];
    const float* mask  = (const float*)d_in[3];
    const float* Wq = (const float*)d_in[4];
    const float* bq = (const float*)d_in[5];
    const float* Wk = (const float*)d_in[6];
    const float* bk = (const float*)d_in[7];
    const float* Wv = (const float*)d_in[8];
    const float* bv = (const float*)d_in[9];
    const float* Wo = (const float*)d_in[10];
    const float* bo = (const float*)d_in[11];

    float* out  = (float*)d_out;
    float* attn = out + (size_t)S_LEN * BATCH * DMODEL;

    static bool attr_set = false;
    if (!attr_set) {
        cudaFuncSetAttribute(scores_exp_kernel,
                             cudaFuncAttributeMaxDynamicSharedMemorySize, SC_TOTAL);
        attr_set = true;
    }

    dim3 pgrid(DMODEL / 128, NROWS / 128);   // (8, 32)

    proj_qkv_kernel<<<pgrid, 256>>>(query,  Wq, bq, 0);
    proj_qkv_kernel<<<pgrid, 256>>>(key_in, Wk, bk, 1);
    proj_qkv_kernel<<<pgrid, 256>>>(value,  Wv, bv, 2);

    scores_exp_kernel<<<dim3(S_LEN / 128, S_LEN / 128, BH), 256, SC_TOTAL>>>(mask);

    sumL_kernel<<<(BH * S_LEN) / 256, 256>>>();

    pv_kernel<<<dim3(S_LEN / 128, BH), 256>>>();

    mean_kernel<<<dim3(S_LEN, BATCH), 256>>>(attn);

    proj_o_kernel<<<pgrid, 256>>>(Wo, bo, out);
}

// round 12
// speedup vs baseline: 1.0490x; 1.0490x over previous
#include <cuda_runtime.h>
#include <cuda_fp16.h>
#include <cstdint>

#define S_LEN  2048
#define BATCH  2
#define DMODEL 1024
#define NHEAD  16
#define DHEAD  64
#define NROWS  (S_LEN * BATCH)
#define BH     (BATCH * NHEAD)

// ---------------------------------------------------------------------------
// Static device scratch
// ---------------------------------------------------------------------------
__device__ __half g_Qh[(size_t)BH * S_LEN * DHEAD];   // [bh][s][d]
__device__ __half g_Kh[(size_t)BH * S_LEN * DHEAD];   // [bh][s][d]
__device__ __half g_Vt[(size_t)BH * DHEAD * S_LEN];   // [bh][d][s]
__device__ __half g_Xh[(size_t)NROWS * DMODEL];       // [token row][D]
__device__ __half g_Ph[(size_t)BH * S_LEN * S_LEN];   // unnormalized exp
__device__ float  g_Lp[(size_t)BH * 16 * S_LEN];      // row-sum partials
__device__ float  g_Li[(size_t)BH * S_LEN];           // 1 / rowsum

__device__ __forceinline__ unsigned pk(float x, float y) {
    __half2 h = __floats2half2_rn(x, y);
    return *(unsigned*)&h;
}

__device__ __forceinline__ void mma16(float d[4], const unsigned a[4], const unsigned b[2]) {
    asm volatile(
        "mma.sync.aligned.m16n8k16.row.col.f32.f16.f16.f32 "
        "{%0,%1,%2,%3},{%4,%5,%6,%7},{%8,%9},{%0,%1,%2,%3};"
        : "+f"(d[0]), "+f"(d[1]), "+f"(d[2]), "+f"(d[3])
        : "r"(a[0]), "r"(a[1]), "r"(a[2]), "r"(a[3]), "r"(b[0]), "r"(b[1]));
}

__device__ __forceinline__ unsigned saddr(const void* p) {
    return (unsigned)__cvta_generic_to_shared(p);
}

__device__ __forceinline__ void ldsm4(unsigned r[4], unsigned addr) {
    asm volatile("ldmatrix.sync.aligned.m8n8.x4.shared.b16 {%0,%1,%2,%3}, [%4];"
        : "=r"(r[0]), "=r"(r[1]), "=r"(r[2]), "=r"(r[3]) : "r"(addr));
}

__device__ __forceinline__ void ldsm2(unsigned r[2], unsigned addr) {
    asm volatile("ldmatrix.sync.aligned.m8n8.x2.shared.b16 {%0,%1}, [%2];"
        : "=r"(r[0]), "=r"(r[1]) : "r"(addr));
}

// ---------------------------------------------------------------------------
// Merged QKV projection: blockIdx.z = mode (0=Q, 1=K, 2=V transposed).
// 128x128 tile, BK=32 halves, 8 warps (2x4), warp 64x32.
// ---------------------------------------------------------------------------
__global__ __launch_bounds__(256, 2) void proj_qkv_kernel(
    const float* __restrict__ Aq, const float* __restrict__ Ak, const float* __restrict__ Av,
    const float* __restrict__ Wq, const float* __restrict__ Wk, const float* __restrict__ Wv,
    const float* __restrict__ bq, const float* __restrict__ bk, const float* __restrict__ bv)
{
    __shared__ unsigned As[128][20];
    __shared__ unsigned Bs[128][20];

    const int mode = blockIdx.z;
    const float* A = (mode == 0) ? Aq : (mode == 1) ? Ak : Av;
    const float* W = (mode == 0) ? Wq : (mode == 1) ? Wk : Wv;
    const float* bias = (mode == 0) ? bq : (mode == 1) ? bk : bv;

    const int tid = threadIdx.x;
    const int m0 = blockIdx.y * 128;
    const int n0 = blockIdx.x * 128;
    const int lane = tid & 31;
    const int warp = tid >> 5;
    const int g = lane >> 2;
    const int t = lane & 3;
    const int wm = warp >> 2;
    const int wn = warp & 3;
    const int arow = ((lane >> 3) & 1) * 8 + (lane & 7);
    const int acol4 = (lane >> 4) * 4;
    const int brow = lane & 7;
    const int bcol4 = ((lane >> 3) & 1) * 4;

    float acc[4][4][4] = {};
    float4 pa[4], pw[4];

#pragma unroll
    for (int i = 0; i < 4; i++) {
        const int idx = tid + 256 * i;
        const int r = idx >> 3;
        const int c = idx & 7;
        pa[i] = *(const float4*)(A + (size_t)(m0 + r) * DMODEL + c * 4);
        pw[i] = *(const float4*)(W + (size_t)(n0 + r) * DMODEL + c * 4);
    }

    for (int k0 = 0; k0 < DMODEL; k0 += 32) {
        __syncthreads();
#pragma unroll
        for (int i = 0; i < 4; i++) {
            const int idx = tid + 256 * i;
            const int r = idx >> 3;
            const int c = idx & 7;
            As[r][c * 2] = pk(pa[i].x, pa[i].y);
            As[r][c * 2 + 1] = pk(pa[i].z, pa[i].w);
            Bs[r][c * 2] = pk(pw[i].x, pw[i].y);
            Bs[r][c * 2 + 1] = pk(pw[i].z, pw[i].w);
        }
        __syncthreads();
        if (k0 + 32 < DMODEL) {
#pragma unroll
            for (int i = 0; i < 4; i++) {
                const int idx = tid + 256 * i;
                const int r = idx >> 3;
                const int c = idx & 7;
                pa[i] = *(const float4*)(A + (size_t)(m0 + r) * DMODEL + k0 + 32 + c * 4);
                pw[i] = *(const float4*)(W + (size_t)(n0 + r) * DMODEL + k0 + 32 + c * 4);
            }
        }
#pragma unroll
        for (int ks = 0; ks < 2; ks++) {
            const int kw = ks * 8;
            unsigned af[4][4], bf[4][2];
#pragma unroll
            for (int mt = 0; mt < 4; mt++)
                ldsm4(af[mt], saddr(&As[wm * 64 + mt * 16 + arow][kw + acol4]));
#pragma unroll
            for (int nt = 0; nt < 4; nt++)
                ldsm2(bf[nt], saddr(&Bs[wn * 32 + nt * 8 + brow][kw + bcol4]));
#pragma unroll
            for (int mt = 0; mt < 4; mt++)
#pragma unroll
                for (int nt = 0; nt < 4; nt++)
                    mma16(acc[mt][nt], af[mt], bf[nt]);
        }
    }

    __half* dstQ = (mode == 0) ? g_Qh : g_Kh;

#pragma unroll
    for (int nt = 0; nt < 4; nt++) {
        const int n = n0 + wn * 32 + nt * 8 + 2 * t;
        const float2 bb = *(const float2*)(bias + n);
        const int h = n >> 6;
        const int d = n & 63;
#pragma unroll
        for (int mt = 0; mt < 4; mt++) {
            const int mlo = m0 + wm * 64 + mt * 16 + g;
            const int s0 = mlo >> 1, b0 = mlo & 1;
            const int s1 = s0 + 4;
            const int bh = b0 * NHEAD + h;
            float v00 = acc[mt][nt][0] + bb.x;
            float v01 = acc[mt][nt][1] + bb.y;
            float v10 = acc[mt][nt][2] + bb.x;
            float v11 = acc[mt][nt][3] + bb.y;
            if (mode != 2) {
                *(__half2*)(dstQ + ((size_t)bh * S_LEN + s0) * DHEAD + d) = __floats2half2_rn(v00, v01);
                *(__half2*)(dstQ + ((size_t)bh * S_LEN + s1) * DHEAD + d) = __floats2half2_rn(v10, v11);
            } else {
                __half* base = g_Vt + (size_t)bh * DHEAD * S_LEN;
                base[(size_t)d * S_LEN + s0] = __float2half_rn(v00);
                base[(size_t)(d + 1) * S_LEN + s0] = __float2half_rn(v01);
                base[(size_t)d * S_LEN + s1] = __float2half_rn(v10);
                base[(size_t)(d + 1) * S_LEN + s1] = __float2half_rn(v11);
            }
        }
    }
}

// ---------------------------------------------------------------------------
// Output projection: out = Xh(fp16) @ Wo^T + bo, fp32 out.
// ---------------------------------------------------------------------------
__global__ __launch_bounds__(256, 2) void proj_o_kernel(
    const float* __restrict__ W, const float* __restrict__ bias,
    float* __restrict__ C)
{
    __shared__ unsigned As[128][20];
    __shared__ unsigned Bs[128][20];

    const int tid = threadIdx.x;
    const int m0 = blockIdx.y * 128;
    const int n0 = blockIdx.x * 128;
    const int lane = tid & 31;
    const int warp = tid >> 5;
    const int g = lane >> 2;
    const int t = lane & 3;
    const int wm = warp >> 2;
    const int wn = warp & 3;
    const int arow = ((lane >> 3) & 1) * 8 + (lane & 7);
    const int acol4 = (lane >> 4) * 4;
    const int brow = lane & 7;
    const int bcol4 = ((lane >> 3) & 1) * 4;

    float acc[4][4][4] = {};
    uint4 pa[2];
    float4 pw[4];

#pragma unroll
    for (int i = 0; i < 2; i++) {
        const int idx = tid + 256 * i;
        const int r = idx >> 2;
        const int c = idx & 3;
        pa[i] = *(const uint4*)(g_Xh + (size_t)(m0 + r) * DMODEL + c * 8);
    }
#pragma unroll
    for (int i = 0; i < 4; i++) {
        const int idx = tid + 256 * i;
        const int r = idx >> 3;
        const int c = idx & 7;
        pw[i] = *(const float4*)(W + (size_t)(n0 + r) * DMODEL + c * 4);
    }

    for (int k0 = 0; k0 < DMODEL; k0 += 32) {
        __syncthreads();
#pragma unroll
        for (int i = 0; i < 2; i++) {
            const int idx = tid + 256 * i;
            const int r = idx >> 2;
            const int c = idx & 3;
            *(uint4*)&As[r][c * 4] = pa[i];
        }
#pragma unroll
        for (int i = 0; i < 4; i++) {
            const int idx = tid + 256 * i;
            const int r = idx >> 3;
            const int c = idx & 7;
            Bs[r][c * 2] = pk(pw[i].x, pw[i].y);
            Bs[r][c * 2 + 1] = pk(pw[i].z, pw[i].w);
        }
        __syncthreads();
        if (k0 + 32 < DMODEL) {
#pragma unroll
            for (int i = 0; i < 2; i++) {
                const int idx = tid + 256 * i;
                const int r = idx >> 2;
                const int c = idx & 3;
                pa[i] = *(const uint4*)(g_Xh + (size_t)(m0 + r) * DMODEL + k0 + 32 + c * 8);
            }
#pragma unroll
            for (int i = 0; i < 4; i++) {
                const int idx = tid + 256 * i;
                const int r = idx >> 3;
                const int c = idx & 7;
                pw[i] = *(const float4*)(W + (size_t)(n0 + r) * DMODEL + k0 + 32 + c * 4);
            }
        }
#pragma unroll
        for (int ks = 0; ks < 2; ks++) {
            const int kw = ks * 8;
            unsigned af[4][4], bf[4][2];
#pragma unroll
            for (int mt = 0; mt < 4; mt++)
                ldsm4(af[mt], saddr(&As[wm * 64 + mt * 16 + arow][kw + acol4]));
#pragma unroll
            for (int nt = 0; nt < 4; nt++)
                ldsm2(bf[nt], saddr(&Bs[wn * 32 + nt * 8 + brow][kw + bcol4]));
#pragma unroll
            for (int mt = 0; mt < 4; mt++)
#pragma unroll
                for (int nt = 0; nt < 4; nt++)
                    mma16(acc[mt][nt], af[mt], bf[nt]);
        }
    }

#pragma unroll
    for (int nt = 0; nt < 4; nt++) {
        const int col = n0 + wn * 32 + nt * 8 + 2 * t;
        const float2 bb = *(const float2*)(bias + col);
#pragma unroll
        for (int mt = 0; mt < 4; mt++) {
            const int mlo = m0 + wm * 64 + mt * 16 + g;
            float2 o0 = {acc[mt][nt][0] + bb.x, acc[mt][nt][1] + bb.y};
            float2 o1 = {acc[mt][nt][2] + bb.x, acc[mt][nt][3] + bb.y};
            *(float2*)(C + (size_t)mlo * DMODEL + col) = o0;
            *(float2*)(C + (size_t)(mlo + 8) * DMODEL + col) = o1;
        }
    }
}

// ---------------------------------------------------------------------------
// Scores + exp: p_u = exp(qk/8 + mask - 4) (fp16) + row-sum partials.
// P tile staged in smem (aliasing the dead Q/K tiles), then coalesced
// 128B-row copy to g_Ph. (R8 version — best measured.)
// ---------------------------------------------------------------------------
__global__ __launch_bounds__(256, 2) void scores_exp_kernel(const float* __restrict__ mask)
{
    __shared__ unsigned Tile[2][128][36];      // [0]=Q, [1]=K; aliased as P stage later
    __shared__ float redL[4][128];

    unsigned (*As)[36] = Tile[0];
    unsigned (*Bs)[36] = Tile[1];
    unsigned* Pst = &Tile[0][0][0];            // P staging: pitch 68 words, 128 rows

    const int tid = threadIdx.x;
    const int bh = blockIdx.z;
    const int b = bh >> 4;
    const int sq0 = blockIdx.y * 128;
    const int st0 = blockIdx.x * 128;
    const int lane = tid & 31;
    const int warp = tid >> 5;
    const int g = lane >> 2;
    const int t = lane & 3;
    const int wm = warp >> 2;
    const int wn = warp & 3;
    const int arow = ((lane >> 3) & 1) * 8 + (lane & 7);
    const int acol4 = (lane >> 4) * 4;
    const int brow = lane & 7;
    const int bcol4 = ((lane >> 3) & 1) * 4;

    const __half* Qh = g_Qh + (size_t)bh * S_LEN * DHEAD;
    const __half* Kh = g_Kh + (size_t)bh * S_LEN * DHEAD;

#pragma unroll
    for (int i = 0; i < 4; i++) {
        const int idx = tid + 256 * i;
        const int r = idx >> 3;
        const int c = idx & 7;
        *(uint4*)&As[r][c * 4] = *(const uint4*)(Qh + (size_t)(sq0 + r) * DHEAD + c * 8);
        *(uint4*)&Bs[r][c * 4] = *(const uint4*)(Kh + (size_t)(st0 + r) * DHEAD + c * 8);
    }
    __syncthreads();

    float acc[4][4][4] = {};
#pragma unroll
    for (int ks = 0; ks < 4; ks++) {
        const int kw = ks * 8;
        unsigned af[4][4], bf[4][2];
#pragma unroll
        for (int mt = 0; mt < 4; mt++)
            ldsm4(af[mt], saddr(&As[wm * 64 + mt * 16 + arow][kw + acol4]));
#pragma unroll
        for (int nt = 0; nt < 4; nt++)
            ldsm2(bf[nt], saddr(&Bs[wn * 32 + nt * 8 + brow][kw + bcol4]));
#pragma unroll
        for (int mt = 0; mt < 4; mt++)
#pragma unroll
            for (int nt = 0; nt < 4; nt++)
                mma16(acc[mt][nt], af[mt], bf[nt]);
    }

    __syncthreads();   // all fragment reads done; Tile region reusable as P stage

    const float scale = 0.125f;
#pragma unroll
    for (int mt = 0; mt < 4; mt++) {
        const int r_lo = wm * 64 + mt * 16 + g;
        const int sq_lo = sq0 + r_lo;
        float rs0 = 0.f, rs1 = 0.f;
#pragma unroll
        for (int nt = 0; nt < 4; nt++) {
            const int cc = wn * 32 + nt * 8 + 2 * t;
            const int st = st0 + cc;
            float2 mk0 = *(const float2*)(mask + ((size_t)b * S_LEN + sq_lo) * S_LEN + st);
            float2 mk1 = *(const float2*)(mask + ((size_t)b * S_LEN + sq_lo + 8) * S_LEN + st);
            float p00 = __expf(acc[mt][nt][0] * scale + mk0.x - 4.0f);
            float p01 = __expf(acc[mt][nt][1] * scale + mk0.y - 4.0f);
            float p10 = __expf(acc[mt][nt][2] * scale + mk1.x - 4.0f);
            float p11 = __expf(acc[mt][nt][3] * scale + mk1.y - 4.0f);
            const int wcol = wn * 16 + nt * 4 + t;      // word col within 64-word row
            Pst[(size_t)r_lo * 68 + wcol] = pk(p00, p01);
            Pst[(size_t)(r_lo + 8) * 68 + wcol] = pk(p10, p11);
            rs0 += p00 + p01;
            rs1 += p10 + p11;
        }
        rs0 += __shfl_xor_sync(0xffffffffu, rs0, 1);
        rs0 += __shfl_xor_sync(0xffffffffu, rs0, 2);
        rs1 += __shfl_xor_sync(0xffffffffu, rs1, 1);
        rs1 += __shfl_xor_sync(0xffffffffu, rs1, 2);
        if (t == 0) {
            redL[wn][r_lo] = rs0;
            redL[wn][r_lo + 8] = rs1;
        }
    }
    __syncthreads();

    // coalesced copy-out: 128 rows x 16 uint4 (256B) per row
#pragma unroll
    for (int i = 0; i < 8; i++) {
        const int idx = tid + 256 * i;       // 0..2047
        const int r = idx >> 4;
        const int j = idx & 15;
        uint4 v = *(const uint4*)&Pst[(size_t)r * 68 + j * 4];
        *(uint4*)(g_Ph + ((size_t)bh * S_LEN + sq0 + r) * S_LEN + st0 + j * 8) = v;
    }

    if (tid < 128) {
        float s = redL[0][tid] + redL[1][tid] + redL[2][tid] + redL[3][tid];
        g_Lp[((size_t)bh * 16 + blockIdx.x) * S_LEN + sq0 + tid] = s;
    }
}

// ---------------------------------------------------------------------------
// Deterministic reduce of row-sum partials -> 1/l
// ---------------------------------------------------------------------------
__global__ __launch_bounds__(256) void sumL_kernel()
{
    const int idx = blockIdx.x * 256 + threadIdx.x;
    const int bh = idx >> 11;
    const int s = idx & 2047;
    float acc = 0.f;
#pragma unroll
    for (int j = 0; j < 16; j++)
        acc += g_Lp[((size_t)bh * 16 + j) * S_LEN + s];
    g_Li[idx] = 1.0f / acc;
}

// ---------------------------------------------------------------------------
// PV: Xh = (P_u @ V) * (1/l). 128x64 tile, BK=32, double-buffered.
// ---------------------------------------------------------------------------
__global__ __launch_bounds__(256, 2) void pv_kernel()
{
    __shared__ unsigned Ps[2][128][20];
    __shared__ unsigned Vs[2][64][20];

    const int tid = threadIdx.x;
    const int bh = blockIdx.y;
    const int b = bh >> 4;
    const int h = bh & 15;
    const int m0 = blockIdx.x * 128;
    const int lane = tid & 31;
    const int warp = tid >> 5;
    const int g = lane >> 2;
    const int t = lane & 3;
    const int wm = warp >> 1;
    const int wn = warp & 1;
    const int arow = ((lane >> 3) & 1) * 8 + (lane & 7);
    const int acol4 = (lane >> 4) * 4;
    const int brow = lane & 7;
    const int bcol4 = ((lane >> 3) & 1) * 4;

    const __half* Ph = g_Ph + (size_t)bh * S_LEN * S_LEN;
    const __half* Vt = g_Vt + (size_t)bh * DHEAD * S_LEN;

    float acc[2][4][4] = {};
    uint4 pp[2], vv;

#pragma unroll
    for (int i = 0; i < 2; i++) {
        const int idx = tid + 256 * i;
        pp[i] = *(const uint4*)(Ph + (size_t)(m0 + (idx >> 2)) * S_LEN + (idx & 3) * 8);
    }
    vv = *(const uint4*)(Vt + (size_t)(tid >> 2) * S_LEN + (tid & 3) * 8);
#pragma unroll
    for (int i = 0; i < 2; i++) {
        const int idx = tid + 256 * i;
        *(uint4*)&Ps[0][idx >> 2][(idx & 3) * 4] = pp[i];
    }
    *(uint4*)&Vs[0][tid >> 2][(tid & 3) * 4] = vv;
    __syncthreads();

    for (int it = 0; it < S_LEN / 32; it++) {
        const int cur = it & 1;
        const int k1 = (it + 1) * 32;
        if (k1 < S_LEN) {
#pragma unroll
            for (int i = 0; i < 2; i++) {
                const int idx = tid + 256 * i;
                pp[i] = *(const uint4*)(Ph + (size_t)(m0 + (idx >> 2)) * S_LEN + k1 + (idx & 3) * 8);
            }
            vv = *(const uint4*)(Vt + (size_t)(tid >> 2) * S_LEN + k1 + (tid & 3) * 8);
        }
#pragma unroll
        for (int ks = 0; ks < 2; ks++) {
            const int kw = ks * 8;
            unsigned af[2][4], bf[4][2];
#pragma unroll
            for (int mt = 0; mt < 2; mt++)
                ldsm4(af[mt], saddr(&Ps[cur][wm * 32 + mt * 16 + arow][kw + acol4]));
#pragma unroll
            for (int nt = 0; nt < 4; nt++)
                ldsm2(bf[nt], saddr(&Vs[cur][wn * 32 + nt * 8 + brow][kw + bcol4]));
#pragma unroll
            for (int mt = 0; mt < 2; mt++)
#pragma unroll
                for (int nt = 0; nt < 4; nt++)
                    mma16(acc[mt][nt], af[mt], bf[nt]);
        }
        if (k1 < S_LEN) {
#pragma unroll
            for (int i = 0; i < 2; i++) {
                const int idx = tid + 256 * i;
                *(uint4*)&Ps[cur ^ 1][idx >> 2][(idx & 3) * 4] = pp[i];
            }
            *(uint4*)&Vs[cur ^ 1][tid >> 2][(tid & 3) * 4] = vv;
        }
        __syncthreads();
    }

#pragma unroll
    for (int mt = 0; mt < 2; mt++) {
        const int mlo = m0 + wm * 32 + mt * 16 + g;
        const float inv0 = g_Li[(size_t)bh * S_LEN + mlo];
        const float inv1 = g_Li[(size_t)bh * S_LEN + mlo + 8];
#pragma unroll
        for (int nt = 0; nt < 4; nt++) {
            const int col = wn * 32 + nt * 8 + 2 * t;
            *(__half2*)(g_Xh + ((size_t)(mlo * BATCH + b)) * DMODEL + h * DHEAD + col) =
                __floats2half2_rn(acc[mt][nt][0] * inv0, acc[mt][nt][1] * inv0);
            *(__half2*)(g_Xh + ((size_t)((mlo + 8) * BATCH + b)) * DMODEL + h * DHEAD + col) =
                __floats2half2_rn(acc[mt][nt][2] * inv1, acc[mt][nt][3] * inv1);
        }
    }
}

// ---------------------------------------------------------------------------
// attn[b][s][t] = sum_h p_u * (1/l) / 16
// ---------------------------------------------------------------------------
__global__ __launch_bounds__(256) void mean_kernel(float* __restrict__ attn)
{
    const int s = blockIdx.x;
    const int b = blockIdx.y;
    const int tid = threadIdx.x;

    float acc[8] = {};
#pragma unroll
    for (int h = 0; h < NHEAD; h++) {
        const int bh = b * NHEAD + h;
        const float inv = g_Li[(size_t)bh * S_LEN + s];
        uint4 u = *(const uint4*)(g_Ph + ((size_t)bh * S_LEN + s) * S_LEN + tid * 8);
        const __half2* hp = (const __half2*)&u;
#pragma unroll
        for (int j = 0; j < 4; j++) {
            float2 f = __half22float2(hp[j]);
            acc[2 * j] += f.x * inv;
            acc[2 * j + 1] += f.y * inv;
        }
    }
    const float im = 1.0f / NHEAD;
    float4 o0 = {acc[0] * im, acc[1] * im, acc[2] * im, acc[3] * im};
    float4 o1 = {acc[4] * im, acc[5] * im, acc[6] * im, acc[7] * im};
    float* dst = attn + ((size_t)b * S_LEN + s) * S_LEN + tid * 8;
    *(float4*)dst = o0;
    *(float4*)(dst + 4) = o1;
}

// ---------------------------------------------------------------------------
// Launch
// ---------------------------------------------------------------------------
extern "C" void kernel_launch(void* const* d_in, const int* in_sizes, int n_in,
                              void* d_out, int out_size)
{
    (void)in_sizes; (void)n_in; (void)out_size;

    const float* query = (const float*)d_in[0];
    const float* key_in = (const float*)d_in[1];
    const float* value = (const float*)d_in[2];
    const float* mask  = (const float*)d_in[3];
    const float* Wq = (const float*)d_in[4];
    const float* bq = (const float*)d_in[5];
    const float* Wk = (const float*)d_in[6];
    const float* bk = (const float*)d_in[7];
    const float* Wv = (const float*)d_in[8];
    const float* bv = (const float*)d_in[9];
    const float* Wo = (const float*)d_in[10];
    const float* bo = (const float*)d_in[11];

    float* out  = (float*)d_out;
    float* attn = out + (size_t)S_LEN * BATCH * DMODEL;

    dim3 pgrid3(DMODEL / 128, NROWS / 128, 3);   // (8, 32, 3) merged QKV

    proj_qkv_kernel<<<pgrid3, 256>>>(query, key_in, value, Wq, Wk, Wv, bq, bk, bv);

    scores_exp_kernel<<<dim3(S_LEN / 128, S_LEN / 128, BH), 256>>>(mask);

    sumL_kernel<<<(BH * S_LEN) / 256, 256>>>();

    pv_kernel<<<dim3(S_LEN / 128, BH), 256>>>();

    mean_kernel<<<dim3(S_LEN, BATCH), 256>>>(attn);

    proj_o_kernel<<<dim3(DMODEL / 128, NROWS / 128), 256>>>(Wo, bo, out);
}

// round 13
// speedup vs baseline: 1.1149x; 1.0628x over previous
#include <cuda_runtime.h>
#include <cuda_fp16.h>
#include <cstdint>

#define S_LEN  2048
#define BATCH  2
#define DMODEL 1024
#define NHEAD  16
#define DHEAD  64
#define NROWS  (S_LEN * BATCH)
#define BH     (BATCH * NHEAD)

// ---------------------------------------------------------------------------
// Static device scratch
// ---------------------------------------------------------------------------
__device__ __half g_Qh[(size_t)BH * S_LEN * DHEAD];   // [bh][s][d]
__device__ __half g_Kh[(size_t)BH * S_LEN * DHEAD];   // [bh][s][d]
__device__ __half g_Vt[(size_t)BH * DHEAD * S_LEN];   // [bh][d][s]
__device__ __half g_Xh[(size_t)NROWS * DMODEL];       // [token row][D]
__device__ __half g_Ph[(size_t)BH * S_LEN * S_LEN];   // unnormalized exp
__device__ float  g_Lp[(size_t)BH * 16 * S_LEN];      // row-sum partials
__device__ float  g_Li[(size_t)BH * S_LEN];           // 1 / rowsum

__device__ __forceinline__ unsigned pk(float x, float y) {
    __half2 h = __floats2half2_rn(x, y);
    return *(unsigned*)&h;
}

__device__ __forceinline__ void mma16(float d[4], const unsigned a[4], const unsigned b[2]) {
    asm volatile(
        "mma.sync.aligned.m16n8k16.row.col.f32.f16.f16.f32 "
        "{%0,%1,%2,%3},{%4,%5,%6,%7},{%8,%9},{%0,%1,%2,%3};"
        : "+f"(d[0]), "+f"(d[1]), "+f"(d[2]), "+f"(d[3])
        : "r"(a[0]), "r"(a[1]), "r"(a[2]), "r"(a[3]), "r"(b[0]), "r"(b[1]));
}

__device__ __forceinline__ unsigned saddr(const void* p) {
    return (unsigned)__cvta_generic_to_shared(p);
}

__device__ __forceinline__ void ldsm4(unsigned r[4], unsigned addr) {
    asm volatile("ldmatrix.sync.aligned.m8n8.x4.shared.b16 {%0,%1,%2,%3}, [%4];"
        : "=r"(r[0]), "=r"(r[1]), "=r"(r[2]), "=r"(r[3]) : "r"(addr));
}

__device__ __forceinline__ void ldsm2(unsigned r[2], unsigned addr) {
    asm volatile("ldmatrix.sync.aligned.m8n8.x2.shared.b16 {%0,%1}, [%2];"
        : "=r"(r[0]), "=r"(r[1]) : "r"(addr));
}

__device__ __forceinline__ void cp_async16(unsigned smem, const void* gptr) {
    asm volatile("cp.async.cg.shared.global [%0], [%1], 16;" :: "r"(smem), "l"(gptr));
}

// ---------------------------------------------------------------------------
// Merged QKV projection: blockIdx.z = mode (0=Q, 1=K, 2=V transposed).
// 128x128 tile, BK=32 halves, 8 warps (2x4), warp 64x32.
// ---------------------------------------------------------------------------
__global__ __launch_bounds__(256, 2) void proj_qkv_kernel(
    const float* __restrict__ Aq, const float* __restrict__ Ak, const float* __restrict__ Av,
    const float* __restrict__ Wq, const float* __restrict__ Wk, const float* __restrict__ Wv,
    const float* __restrict__ bq, const float* __restrict__ bk, const float* __restrict__ bv)
{
    __shared__ unsigned As[128][20];
    __shared__ unsigned Bs[128][20];

    const int mode = blockIdx.z;
    const float* A = (mode == 0) ? Aq : (mode == 1) ? Ak : Av;
    const float* W = (mode == 0) ? Wq : (mode == 1) ? Wk : Wv;
    const float* bias = (mode == 0) ? bq : (mode == 1) ? bk : bv;

    const int tid = threadIdx.x;
    const int m0 = blockIdx.y * 128;
    const int n0 = blockIdx.x * 128;
    const int lane = tid & 31;
    const int warp = tid >> 5;
    const int g = lane >> 2;
    const int t = lane & 3;
    const int wm = warp >> 2;
    const int wn = warp & 3;
    const int arow = ((lane >> 3) & 1) * 8 + (lane & 7);
    const int acol4 = (lane >> 4) * 4;
    const int brow = lane & 7;
    const int bcol4 = ((lane >> 3) & 1) * 4;

    float acc[4][4][4] = {};
    float4 pa[4], pw[4];

#pragma unroll
    for (int i = 0; i < 4; i++) {
        const int idx = tid + 256 * i;
        const int r = idx >> 3;
        const int c = idx & 7;
        pa[i] = *(const float4*)(A + (size_t)(m0 + r) * DMODEL + c * 4);
        pw[i] = *(const float4*)(W + (size_t)(n0 + r) * DMODEL + c * 4);
    }

    for (int k0 = 0; k0 < DMODEL; k0 += 32) {
        __syncthreads();
#pragma unroll
        for (int i = 0; i < 4; i++) {
            const int idx = tid + 256 * i;
            const int r = idx >> 3;
            const int c = idx & 7;
            As[r][c * 2] = pk(pa[i].x, pa[i].y);
            As[r][c * 2 + 1] = pk(pa[i].z, pa[i].w);
            Bs[r][c * 2] = pk(pw[i].x, pw[i].y);
            Bs[r][c * 2 + 1] = pk(pw[i].z, pw[i].w);
        }
        __syncthreads();
        if (k0 + 32 < DMODEL) {
#pragma unroll
            for (int i = 0; i < 4; i++) {
                const int idx = tid + 256 * i;
                const int r = idx >> 3;
                const int c = idx & 7;
                pa[i] = *(const float4*)(A + (size_t)(m0 + r) * DMODEL + k0 + 32 + c * 4);
                pw[i] = *(const float4*)(W + (size_t)(n0 + r) * DMODEL + k0 + 32 + c * 4);
            }
        }
#pragma unroll
        for (int ks = 0; ks < 2; ks++) {
            const int kw = ks * 8;
            unsigned af[4][4], bf[4][2];
#pragma unroll
            for (int mt = 0; mt < 4; mt++)
                ldsm4(af[mt], saddr(&As[wm * 64 + mt * 16 + arow][kw + acol4]));
#pragma unroll
            for (int nt = 0; nt < 4; nt++)
                ldsm2(bf[nt], saddr(&Bs[wn * 32 + nt * 8 + brow][kw + bcol4]));
#pragma unroll
            for (int mt = 0; mt < 4; mt++)
#pragma unroll
                for (int nt = 0; nt < 4; nt++)
                    mma16(acc[mt][nt], af[mt], bf[nt]);
        }
    }

    __half* dstQ = (mode == 0) ? g_Qh : g_Kh;

#pragma unroll
    for (int nt = 0; nt < 4; nt++) {
        const int n = n0 + wn * 32 + nt * 8 + 2 * t;
        const float2 bb = *(const float2*)(bias + n);
        const int h = n >> 6;
        const int d = n & 63;
#pragma unroll
        for (int mt = 0; mt < 4; mt++) {
            const int mlo = m0 + wm * 64 + mt * 16 + g;
            const int s0 = mlo >> 1, b0 = mlo & 1;
            const int s1 = s0 + 4;
            const int bh = b0 * NHEAD + h;
            float v00 = acc[mt][nt][0] + bb.x;
            float v01 = acc[mt][nt][1] + bb.y;
            float v10 = acc[mt][nt][2] + bb.x;
            float v11 = acc[mt][nt][3] + bb.y;
            if (mode != 2) {
                *(__half2*)(dstQ + ((size_t)bh * S_LEN + s0) * DHEAD + d) = __floats2half2_rn(v00, v01);
                *(__half2*)(dstQ + ((size_t)bh * S_LEN + s1) * DHEAD + d) = __floats2half2_rn(v10, v11);
            } else {
                __half* base = g_Vt + (size_t)bh * DHEAD * S_LEN;
                base[(size_t)d * S_LEN + s0] = __float2half_rn(v00);
                base[(size_t)(d + 1) * S_LEN + s0] = __float2half_rn(v01);
                base[(size_t)d * S_LEN + s1] = __float2half_rn(v10);
                base[(size_t)(d + 1) * S_LEN + s1] = __float2half_rn(v11);
            }
        }
    }
}

// ---------------------------------------------------------------------------
// Output projection: out = Xh(fp16) @ Wo^T + bo, fp32 out.
// ---------------------------------------------------------------------------
__global__ __launch_bounds__(256, 2) void proj_o_kernel(
    const float* __restrict__ W, const float* __restrict__ bias,
    float* __restrict__ C)
{
    __shared__ unsigned As[128][20];
    __shared__ unsigned Bs[128][20];

    const int tid = threadIdx.x;
    const int m0 = blockIdx.y * 128;
    const int n0 = blockIdx.x * 128;
    const int lane = tid & 31;
    const int warp = tid >> 5;
    const int g = lane >> 2;
    const int t = lane & 3;
    const int wm = warp >> 2;
    const int wn = warp & 3;
    const int arow = ((lane >> 3) & 1) * 8 + (lane & 7);
    const int acol4 = (lane >> 4) * 4;
    const int brow = lane & 7;
    const int bcol4 = ((lane >> 3) & 1) * 4;

    float acc[4][4][4] = {};
    uint4 pa[2];
    float4 pw[4];

#pragma unroll
    for (int i = 0; i < 2; i++) {
        const int idx = tid + 256 * i;
        const int r = idx >> 2;
        const int c = idx & 3;
        pa[i] = *(const uint4*)(g_Xh + (size_t)(m0 + r) * DMODEL + c * 8);
    }
#pragma unroll
    for (int i = 0; i < 4; i++) {
        const int idx = tid + 256 * i;
        const int r = idx >> 3;
        const int c = idx & 7;
        pw[i] = *(const float4*)(W + (size_t)(n0 + r) * DMODEL + c * 4);
    }

    for (int k0 = 0; k0 < DMODEL; k0 += 32) {
        __syncthreads();
#pragma unroll
        for (int i = 0; i < 2; i++) {
            const int idx = tid + 256 * i;
            const int r = idx >> 2;
            const int c = idx & 3;
            *(uint4*)&As[r][c * 4] = pa[i];
        }
#pragma unroll
        for (int i = 0; i < 4; i++) {
            const int idx = tid + 256 * i;
            const int r = idx >> 3;
            const int c = idx & 7;
            Bs[r][c * 2] = pk(pw[i].x, pw[i].y);
            Bs[r][c * 2 + 1] = pk(pw[i].z, pw[i].w);
        }
        __syncthreads();
        if (k0 + 32 < DMODEL) {
#pragma unroll
            for (int i = 0; i < 2; i++) {
                const int idx = tid + 256 * i;
                const int r = idx >> 2;
                const int c = idx & 3;
                pa[i] = *(const uint4*)(g_Xh + (size_t)(m0 + r) * DMODEL + k0 + 32 + c * 8);
            }
#pragma unroll
            for (int i = 0; i < 4; i++) {
                const int idx = tid + 256 * i;
                const int r = idx >> 3;
                const int c = idx & 7;
                pw[i] = *(const float4*)(W + (size_t)(n0 + r) * DMODEL + k0 + 32 + c * 4);
            }
        }
#pragma unroll
        for (int ks = 0; ks < 2; ks++) {
            const int kw = ks * 8;
            unsigned af[4][4], bf[4][2];
#pragma unroll
            for (int mt = 0; mt < 4; mt++)
                ldsm4(af[mt], saddr(&As[wm * 64 + mt * 16 + arow][kw + acol4]));
#pragma unroll
            for (int nt = 0; nt < 4; nt++)
                ldsm2(bf[nt], saddr(&Bs[wn * 32 + nt * 8 + brow][kw + bcol4]));
#pragma unroll
            for (int mt = 0; mt < 4; mt++)
#pragma unroll
                for (int nt = 0; nt < 4; nt++)
                    mma16(acc[mt][nt], af[mt], bf[nt]);
        }
    }

#pragma unroll
    for (int nt = 0; nt < 4; nt++) {
        const int col = n0 + wn * 32 + nt * 8 + 2 * t;
        const float2 bb = *(const float2*)(bias + col);
#pragma unroll
        for (int mt = 0; mt < 4; mt++) {
            const int mlo = m0 + wm * 64 + mt * 16 + g;
            float2 o0 = {acc[mt][nt][0] + bb.x, acc[mt][nt][1] + bb.y};
            float2 o1 = {acc[mt][nt][2] + bb.x, acc[mt][nt][3] + bb.y};
            *(float2*)(C + (size_t)mlo * DMODEL + col) = o0;
            *(float2*)(C + (size_t)(mlo + 8) * DMODEL + col) = o1;
        }
    }
}

// ---------------------------------------------------------------------------
// Scores + exp: p_u = exp(qk/8 + mask - 4) (fp16) + row-sum partials.
// P tile staged in smem (aliasing the dead Q/K tiles), then coalesced
// 128B-row copy to g_Ph. (R8 version — best measured.)
// ---------------------------------------------------------------------------
__global__ __launch_bounds__(256, 2) void scores_exp_kernel(const float* __restrict__ mask)
{
    __shared__ unsigned Tile[2][128][36];      // [0]=Q, [1]=K; aliased as P stage later
    __shared__ float redL[4][128];

    unsigned (*As)[36] = Tile[0];
    unsigned (*Bs)[36] = Tile[1];
    unsigned* Pst = &Tile[0][0][0];            // P staging: pitch 68 words, 128 rows

    const int tid = threadIdx.x;
    const int bh = blockIdx.z;
    const int b = bh >> 4;
    const int sq0 = blockIdx.y * 128;
    const int st0 = blockIdx.x * 128;
    const int lane = tid & 31;
    const int warp = tid >> 5;
    const int g = lane >> 2;
    const int t = lane & 3;
    const int wm = warp >> 2;
    const int wn = warp & 3;
    const int arow = ((lane >> 3) & 1) * 8 + (lane & 7);
    const int acol4 = (lane >> 4) * 4;
    const int brow = lane & 7;
    const int bcol4 = ((lane >> 3) & 1) * 4;

    const __half* Qh = g_Qh + (size_t)bh * S_LEN * DHEAD;
    const __half* Kh = g_Kh + (size_t)bh * S_LEN * DHEAD;

#pragma unroll
    for (int i = 0; i < 4; i++) {
        const int idx = tid + 256 * i;
        const int r = idx >> 3;
        const int c = idx & 7;
        *(uint4*)&As[r][c * 4] = *(const uint4*)(Qh + (size_t)(sq0 + r) * DHEAD + c * 8);
        *(uint4*)&Bs[r][c * 4] = *(const uint4*)(Kh + (size_t)(st0 + r) * DHEAD + c * 8);
    }
    __syncthreads();

    float acc[4][4][4] = {};
#pragma unroll
    for (int ks = 0; ks < 4; ks++) {
        const int kw = ks * 8;
        unsigned af[4][4], bf[4][2];
#pragma unroll
        for (int mt = 0; mt < 4; mt++)
            ldsm4(af[mt], saddr(&As[wm * 64 + mt * 16 + arow][kw + acol4]));
#pragma unroll
        for (int nt = 0; nt < 4; nt++)
            ldsm2(bf[nt], saddr(&Bs[wn * 32 + nt * 8 + brow][kw + bcol4]));
#pragma unroll
        for (int mt = 0; mt < 4; mt++)
#pragma unroll
            for (int nt = 0; nt < 4; nt++)
                mma16(acc[mt][nt], af[mt], bf[nt]);
    }

    __syncthreads();   // all fragment reads done; Tile region reusable as P stage

    const float scale = 0.125f;
#pragma unroll
    for (int mt = 0; mt < 4; mt++) {
        const int r_lo = wm * 64 + mt * 16 + g;
        const int sq_lo = sq0 + r_lo;
        float rs0 = 0.f, rs1 = 0.f;
#pragma unroll
        for (int nt = 0; nt < 4; nt++) {
            const int cc = wn * 32 + nt * 8 + 2 * t;
            const int st = st0 + cc;
            float2 mk0 = *(const float2*)(mask + ((size_t)b * S_LEN + sq_lo) * S_LEN + st);
            float2 mk1 = *(const float2*)(mask + ((size_t)b * S_LEN + sq_lo + 8) * S_LEN + st);
            float p00 = __expf(acc[mt][nt][0] * scale + mk0.x - 4.0f);
            float p01 = __expf(acc[mt][nt][1] * scale + mk0.y - 4.0f);
            float p10 = __expf(acc[mt][nt][2] * scale + mk1.x - 4.0f);
            float p11 = __expf(acc[mt][nt][3] * scale + mk1.y - 4.0f);
            const int wcol = wn * 16 + nt * 4 + t;      // word col within 64-word row
            Pst[(size_t)r_lo * 68 + wcol] = pk(p00, p01);
            Pst[(size_t)(r_lo + 8) * 68 + wcol] = pk(p10, p11);
            rs0 += p00 + p01;
            rs1 += p10 + p11;
        }
        rs0 += __shfl_xor_sync(0xffffffffu, rs0, 1);
        rs0 += __shfl_xor_sync(0xffffffffu, rs0, 2);
        rs1 += __shfl_xor_sync(0xffffffffu, rs1, 1);
        rs1 += __shfl_xor_sync(0xffffffffu, rs1, 2);
        if (t == 0) {
            redL[wn][r_lo] = rs0;
            redL[wn][r_lo + 8] = rs1;
        }
    }
    __syncthreads();

    // coalesced copy-out: 128 rows x 16 uint4 (256B) per row
#pragma unroll
    for (int i = 0; i < 8; i++) {
        const int idx = tid + 256 * i;       // 0..2047
        const int r = idx >> 4;
        const int j = idx & 15;
        uint4 v = *(const uint4*)&Pst[(size_t)r * 68 + j * 4];
        *(uint4*)(g_Ph + ((size_t)bh * S_LEN + sq0 + r) * S_LEN + st0 + j * 8) = v;
    }

    if (tid < 128) {
        float s = redL[0][tid] + redL[1][tid] + redL[2][tid] + redL[3][tid];
        g_Lp[((size_t)bh * 16 + blockIdx.x) * S_LEN + sq0 + tid] = s;
    }
}

// ---------------------------------------------------------------------------
// Deterministic reduce of row-sum partials -> 1/l
// ---------------------------------------------------------------------------
__global__ __launch_bounds__(256) void sumL_kernel()
{
    const int idx = blockIdx.x * 256 + threadIdx.x;
    const int bh = idx >> 11;
    const int s = idx & 2047;
    float acc = 0.f;
#pragma unroll
    for (int j = 0; j < 16; j++)
        acc += g_Lp[((size_t)bh * 16 + j) * S_LEN + s];
    g_Li[idx] = 1.0f / acc;
}

// ---------------------------------------------------------------------------
// PV: Xh = (P_u @ V) * (1/l). 128x64 tile, BK=32, 4-stage cp.async pipeline.
// ---------------------------------------------------------------------------
#define PV_NIT (S_LEN / 32)

__global__ __launch_bounds__(256, 2) void pv_kernel()
{
    __shared__ unsigned Ps[4][128][20];
    __shared__ unsigned Vs[4][64][20];

    const int tid = threadIdx.x;
    const int bh = blockIdx.y;
    const int b = bh >> 4;
    const int h = bh & 15;
    const int m0 = blockIdx.x * 128;
    const int lane = tid & 31;
    const int warp = tid >> 5;
    const int g = lane >> 2;
    const int t = lane & 3;
    const int wm = warp >> 1;
    const int wn = warp & 1;
    const int arow = ((lane >> 3) & 1) * 8 + (lane & 7);
    const int acol4 = (lane >> 4) * 4;
    const int brow = lane & 7;
    const int bcol4 = ((lane >> 3) & 1) * 4;

    const __half* Ph = g_Ph + (size_t)bh * S_LEN * S_LEN;
    const __half* Vt = g_Vt + (size_t)bh * DHEAD * S_LEN;

    // per-thread load coordinates (same every stage)
    const int pr0 = tid >> 2;                 // P rows for i=0
    const int pr1 = (tid + 256) >> 2;         // P rows for i=1
    const int pc = (tid & 3) * 8;             // half-offset within 32-half chunk
    const int vr = tid >> 2;                  // V row (0..63)

    auto load_stage = [&](int stage, int k) {
        cp_async16(saddr(&Ps[stage][pr0][(tid & 3) * 4]),
                   Ph + (size_t)(m0 + pr0) * S_LEN + k + pc);
        cp_async16(saddr(&Ps[stage][pr1][(tid & 3) * 4]),
                   Ph + (size_t)(m0 + pr1) * S_LEN + k + pc);
        cp_async16(saddr(&Vs[stage][vr][(tid & 3) * 4]),
                   Vt + (size_t)vr * S_LEN + k + pc);
    };

    // prologue: fill 3 stages
#pragma unroll
    for (int s = 0; s < 3; s++) {
        load_stage(s, s * 32);
        asm volatile("cp.async.commit_group;");
    }

    float acc[2][4][4] = {};

    for (int it = 0; it < PV_NIT; it++) {
        const int cur = it & 3;
        asm volatile("cp.async.wait_group 2;");
        __syncthreads();   // stage cur visible to all; stage (it+3)&3 free (computed at it-1)

        if (it + 3 < PV_NIT)
            load_stage((it + 3) & 3, (it + 3) * 32);
        asm volatile("cp.async.commit_group;");

#pragma unroll
        for (int ks = 0; ks < 2; ks++) {
            const int kw = ks * 8;
            unsigned af[2][4], bf[4][2];
#pragma unroll
            for (int mt = 0; mt < 2; mt++)
                ldsm4(af[mt], saddr(&Ps[cur][wm * 32 + mt * 16 + arow][kw + acol4]));
#pragma unroll
            for (int nt = 0; nt < 4; nt++)
                ldsm2(bf[nt], saddr(&Vs[cur][wn * 32 + nt * 8 + brow][kw + bcol4]));
#pragma unroll
            for (int mt = 0; mt < 2; mt++)
#pragma unroll
                for (int nt = 0; nt < 4; nt++)
                    mma16(acc[mt][nt], af[mt], bf[nt]);
        }
    }

#pragma unroll
    for (int mt = 0; mt < 2; mt++) {
        const int mlo = m0 + wm * 32 + mt * 16 + g;
        const float inv0 = g_Li[(size_t)bh * S_LEN + mlo];
        const float inv1 = g_Li[(size_t)bh * S_LEN + mlo + 8];
#pragma unroll
        for (int nt = 0; nt < 4; nt++) {
            const int col = wn * 32 + nt * 8 + 2 * t;
            *(__half2*)(g_Xh + ((size_t)(mlo * BATCH + b)) * DMODEL + h * DHEAD + col) =
                __floats2half2_rn(acc[mt][nt][0] * inv0, acc[mt][nt][1] * inv0);
            *(__half2*)(g_Xh + ((size_t)((mlo + 8) * BATCH + b)) * DMODEL + h * DHEAD + col) =
                __floats2half2_rn(acc[mt][nt][2] * inv1, acc[mt][nt][3] * inv1);
        }
    }
}

// ---------------------------------------------------------------------------
// attn[b][s][t] = sum_h p_u * (1/l) / 16
// ---------------------------------------------------------------------------
__global__ __launch_bounds__(256) void mean_kernel(float* __restrict__ attn)
{
    const int s = blockIdx.x;
    const int b = blockIdx.y;
    const int tid = threadIdx.x;

    float acc[8] = {};
#pragma unroll
    for (int h = 0; h < NHEAD; h++) {
        const int bh = b * NHEAD + h;
        const float inv = g_Li[(size_t)bh * S_LEN + s];
        uint4 u = *(const uint4*)(g_Ph + ((size_t)bh * S_LEN + s) * S_LEN + tid * 8);
        const __half2* hp = (const __half2*)&u;
#pragma unroll
        for (int j = 0; j < 4; j++) {
            float2 f = __half22float2(hp[j]);
            acc[2 * j] += f.x * inv;
            acc[2 * j + 1] += f.y * inv;
        }
    }
    const float im = 1.0f / NHEAD;
    float4 o0 = {acc[0] * im, acc[1] * im, acc[2] * im, acc[3] * im};
    float4 o1 = {acc[4] * im, acc[5] * im, acc[6] * im, acc[7] * im};
    float* dst = attn + ((size_t)b * S_LEN + s) * S_LEN + tid * 8;
    *(float4*)dst = o0;
    *(float4*)(dst + 4) = o1;
}

// ---------------------------------------------------------------------------
// Launch
// ---------------------------------------------------------------------------
extern "C" void kernel_launch(void* const* d_in, const int* in_sizes, int n_in,
                              void* d_out, int out_size)
{
    (void)in_sizes; (void)n_in; (void)out_size;

    const float* query = (const float*)d_in[0];
    const float* key_in = (const float*)d_in[1];
    const float* value = (const float*)d_in[2];
    const float* mask  = (const float*)d_in[3];
    const float* Wq = (const float*)d_in[4];
    const float* bq = (const float*)d_in[5];
    const float* Wk = (const float*)d_in[6];
    const float* bk = (const float*)d_in[7];
    const float* Wv = (const float*)d_in[8];
    const float* bv = (const float*)d_in[9];
    const float* Wo = (const float*)d_in[10];
    const float* bo = (const float*)d_in[11];

    float* out  = (float*)d_out;
    float* attn = out + (size_t)S_LEN * BATCH * DMODEL;

    dim3 pgrid3(DMODEL / 128, NROWS / 128, 3);   // (8, 32, 3) merged QKV

    proj_qkv_kernel<<<pgrid3, 256>>>(query, key_in, value, Wq, Wk, Wv, bq, bk, bv);

    scores_exp_kernel<<<dim3(S_LEN / 128, S_LEN / 128, BH), 256>>>(mask);

    sumL_kernel<<<(BH * S_LEN) / 256, 256>>>();

    pv_kernel<<<dim3(S_LEN / 128, BH), 256>>>();

    mean_kernel<<<dim3(S_LEN, BATCH), 256>>>(attn);

    proj_o_kernel<<<dim3(DMODEL / 128, NROWS / 128), 256>>>(Wo, bo, out);
}

// round 14
// speedup vs baseline: 1.1717x; 1.0509x over previous
#include <cuda_runtime.h>
#include <cuda_fp16.h>
#include <cstdint>

#define S_LEN  2048
#define BATCH  2
#define DMODEL 1024
#define NHEAD  16
#define DHEAD  64
#define NROWS  (S_LEN * BATCH)
#define BH     (BATCH * NHEAD)
#define NIN    (NROWS * DMODEL)
#define NW     (DMODEL * DMODEL)

// ---------------------------------------------------------------------------
// Static device scratch
// ---------------------------------------------------------------------------
__device__ __half g_Ah[(size_t)3 * NIN];              // fp16 q/k/v inputs
__device__ __half g_Wh[(size_t)4 * NW];               // fp16 Wq,Wk,Wv,Wo
__device__ __half g_Qh[(size_t)BH * S_LEN * DHEAD];   // [bh][s][d]
__device__ __half g_Kh[(size_t)BH * S_LEN * DHEAD];   // [bh][s][d]
__device__ __half g_Vt[(size_t)BH * DHEAD * S_LEN];   // [bh][d][s]
__device__ __half g_Xh[(size_t)NROWS * DMODEL];       // [token row][D]
__device__ __half g_Ph[(size_t)BH * S_LEN * S_LEN];   // unnormalized exp
__device__ float  g_Lp[(size_t)BH * 16 * S_LEN];      // row-sum partials
__device__ float  g_Li[(size_t)BH * S_LEN];           // 1 / rowsum

__device__ __forceinline__ unsigned pk(float x, float y) {
    __half2 h = __floats2half2_rn(x, y);
    return *(unsigned*)&h;
}

__device__ __forceinline__ void mma16(float d[4], const unsigned a[4], const unsigned b[2]) {
    asm volatile(
        "mma.sync.aligned.m16n8k16.row.col.f32.f16.f16.f32 "
        "{%0,%1,%2,%3},{%4,%5,%6,%7},{%8,%9},{%0,%1,%2,%3};"
        : "+f"(d[0]), "+f"(d[1]), "+f"(d[2]), "+f"(d[3])
        : "r"(a[0]), "r"(a[1]), "r"(a[2]), "r"(a[3]), "r"(b[0]), "r"(b[1]));
}

__device__ __forceinline__ unsigned saddr(const void* p) {
    return (unsigned)__cvta_generic_to_shared(p);
}

__device__ __forceinline__ void ldsm4(unsigned r[4], unsigned addr) {
    asm volatile("ldmatrix.sync.aligned.m8n8.x4.shared.b16 {%0,%1,%2,%3}, [%4];"
        : "=r"(r[0]), "=r"(r[1]), "=r"(r[2]), "=r"(r[3]) : "r"(addr));
}

__device__ __forceinline__ void ldsm2(unsigned r[2], unsigned addr) {
    asm volatile("ldmatrix.sync.aligned.m8n8.x2.shared.b16 {%0,%1}, [%2];"
        : "=r"(r[0]), "=r"(r[1]) : "r"(addr));
}

__device__ __forceinline__ void cp_async16(unsigned smem, const void* gptr) {
    asm volatile("cp.async.cg.shared.global [%0], [%1], 16;" :: "r"(smem), "l"(gptr));
}

// ---------------------------------------------------------------------------
// prep: fp32 -> fp16 for 3 inputs (4M each) + 4 weights (1M each).
// blockIdx.y selects the tensor; 8 elems/thread.
// ---------------------------------------------------------------------------
__global__ __launch_bounds__(256) void prep_kernel(
    const float* __restrict__ s0, const float* __restrict__ s1, const float* __restrict__ s2,
    const float* __restrict__ s3, const float* __restrict__ s4, const float* __restrict__ s5,
    const float* __restrict__ s6)
{
    const int y = blockIdx.y;
    const float* src = (y == 0) ? s0 : (y == 1) ? s1 : (y == 2) ? s2 :
                       (y == 3) ? s3 : (y == 4) ? s4 : (y == 5) ? s5 : s6;
    const int n = (y < 3) ? NIN : NW;
    __half* dst = (y < 3) ? (g_Ah + (size_t)y * NIN) : (g_Wh + (size_t)(y - 3) * NW);

    const int i = (blockIdx.x * 256 + threadIdx.x) * 8;
    if (i < n) {
        float4 v0 = *(const float4*)(src + i);
        float4 v1 = *(const float4*)(src + i + 4);
        uint4 u;
        u.x = pk(v0.x, v0.y); u.y = pk(v0.z, v0.w);
        u.z = pk(v1.x, v1.y); u.w = pk(v1.z, v1.w);
        *(uint4*)(dst + i) = u;
    }
}

// ---------------------------------------------------------------------------
// Merged QKV projection, fp16 inputs, 3-stage cp.async pipeline.
// blockIdx.z = mode (0=Q, 1=K, 2=V transposed). 128x128 tile, BK=32 halves.
// ---------------------------------------------------------------------------
__global__ __launch_bounds__(256, 2) void proj_qkv_kernel(
    const float* __restrict__ bq, const float* __restrict__ bk, const float* __restrict__ bv)
{
    __shared__ unsigned As[3][128][20];
    __shared__ unsigned Bs[3][128][20];

    const int mode = blockIdx.z;
    const __half* A = g_Ah + (size_t)mode * NIN;
    const __half* W = g_Wh + (size_t)mode * NW;
    const float* bias = (mode == 0) ? bq : (mode == 1) ? bk : bv;

    const int tid = threadIdx.x;
    const int m0 = blockIdx.y * 128;
    const int n0 = blockIdx.x * 128;
    const int lane = tid & 31;
    const int warp = tid >> 5;
    const int g = lane >> 2;
    const int t = lane & 3;
    const int wm = warp >> 2;
    const int wn = warp & 3;
    const int arow = ((lane >> 3) & 1) * 8 + (lane & 7);
    const int acol4 = (lane >> 4) * 4;
    const int brow = lane & 7;
    const int bcol4 = ((lane >> 3) & 1) * 4;

    const int lr0 = tid >> 2;                // rows for i=0 (0..63)
    const int lr1 = (tid + 256) >> 2;        // rows for i=1 (64..127)
    const int lc = tid & 3;                  // chunk 0..3 (8 halves each)

    auto load_stage = [&](int s, int kh) {
        cp_async16(saddr(&As[s][lr0][lc * 4]), A + (size_t)(m0 + lr0) * DMODEL + kh + lc * 8);
        cp_async16(saddr(&As[s][lr1][lc * 4]), A + (size_t)(m0 + lr1) * DMODEL + kh + lc * 8);
        cp_async16(saddr(&Bs[s][lr0][lc * 4]), W + (size_t)(n0 + lr0) * DMODEL + kh + lc * 8);
        cp_async16(saddr(&Bs[s][lr1][lc * 4]), W + (size_t)(n0 + lr1) * DMODEL + kh + lc * 8);
    };

#pragma unroll
    for (int s = 0; s < 2; s++) {
        load_stage(s, s * 32);
        asm volatile("cp.async.commit_group;");
    }

    float acc[4][4][4] = {};

    for (int it = 0; it < DMODEL / 32; it++) {
        const int cur = it % 3;
        asm volatile("cp.async.wait_group 1;");
        __syncthreads();

        if (it + 2 < DMODEL / 32)
            load_stage((it + 2) % 3, (it + 2) * 32);
        asm volatile("cp.async.commit_group;");

#pragma unroll
        for (int ks = 0; ks < 2; ks++) {
            const int kw = ks * 8;
            unsigned af[4][4], bf[4][2];
#pragma unroll
            for (int mt = 0; mt < 4; mt++)
                ldsm4(af[mt], saddr(&As[cur][wm * 64 + mt * 16 + arow][kw + acol4]));
#pragma unroll
            for (int nt = 0; nt < 4; nt++)
                ldsm2(bf[nt], saddr(&Bs[cur][wn * 32 + nt * 8 + brow][kw + bcol4]));
#pragma unroll
            for (int mt = 0; mt < 4; mt++)
#pragma unroll
                for (int nt = 0; nt < 4; nt++)
                    mma16(acc[mt][nt], af[mt], bf[nt]);
        }
    }

    __half* dstQ = (mode == 0) ? g_Qh : g_Kh;

#pragma unroll
    for (int nt = 0; nt < 4; nt++) {
        const int n = n0 + wn * 32 + nt * 8 + 2 * t;
        const float2 bb = *(const float2*)(bias + n);
        const int h = n >> 6;
        const int d = n & 63;
#pragma unroll
        for (int mt = 0; mt < 4; mt++) {
            const int mlo = m0 + wm * 64 + mt * 16 + g;
            const int s0 = mlo >> 1, b0 = mlo & 1;
            const int s1 = s0 + 4;
            const int bh = b0 * NHEAD + h;
            float v00 = acc[mt][nt][0] + bb.x;
            float v01 = acc[mt][nt][1] + bb.y;
            float v10 = acc[mt][nt][2] + bb.x;
            float v11 = acc[mt][nt][3] + bb.y;
            if (mode != 2) {
                *(__half2*)(dstQ + ((size_t)bh * S_LEN + s0) * DHEAD + d) = __floats2half2_rn(v00, v01);
                *(__half2*)(dstQ + ((size_t)bh * S_LEN + s1) * DHEAD + d) = __floats2half2_rn(v10, v11);
            } else {
                __half* base = g_Vt + (size_t)bh * DHEAD * S_LEN;
                base[(size_t)d * S_LEN + s0] = __float2half_rn(v00);
                base[(size_t)(d + 1) * S_LEN + s0] = __float2half_rn(v01);
                base[(size_t)d * S_LEN + s1] = __float2half_rn(v10);
                base[(size_t)(d + 1) * S_LEN + s1] = __float2half_rn(v11);
            }
        }
    }
}

// ---------------------------------------------------------------------------
// Output projection, fp16 inputs, 3-stage cp.async: out = Xh @ Wo^T + bo.
// ---------------------------------------------------------------------------
__global__ __launch_bounds__(256, 2) void proj_o_kernel(
    const float* __restrict__ bias, float* __restrict__ C)
{
    __shared__ unsigned As[3][128][20];
    __shared__ unsigned Bs[3][128][20];

    const __half* A = g_Xh;
    const __half* W = g_Wh + (size_t)3 * NW;

    const int tid = threadIdx.x;
    const int m0 = blockIdx.y * 128;
    const int n0 = blockIdx.x * 128;
    const int lane = tid & 31;
    const int warp = tid >> 5;
    const int g = lane >> 2;
    const int t = lane & 3;
    const int wm = warp >> 2;
    const int wn = warp & 3;
    const int arow = ((lane >> 3) & 1) * 8 + (lane & 7);
    const int acol4 = (lane >> 4) * 4;
    const int brow = lane & 7;
    const int bcol4 = ((lane >> 3) & 1) * 4;

    const int lr0 = tid >> 2;
    const int lr1 = (tid + 256) >> 2;
    const int lc = tid & 3;

    auto load_stage = [&](int s, int kh) {
        cp_async16(saddr(&As[s][lr0][lc * 4]), A + (size_t)(m0 + lr0) * DMODEL + kh + lc * 8);
        cp_async16(saddr(&As[s][lr1][lc * 4]), A + (size_t)(m0 + lr1) * DMODEL + kh + lc * 8);
        cp_async16(saddr(&Bs[s][lr0][lc * 4]), W + (size_t)(n0 + lr0) * DMODEL + kh + lc * 8);
        cp_async16(saddr(&Bs[s][lr1][lc * 4]), W + (size_t)(n0 + lr1) * DMODEL + kh + lc * 8);
    };

#pragma unroll
    for (int s = 0; s < 2; s++) {
        load_stage(s, s * 32);
        asm volatile("cp.async.commit_group;");
    }

    float acc[4][4][4] = {};

    for (int it = 0; it < DMODEL / 32; it++) {
        const int cur = it % 3;
        asm volatile("cp.async.wait_group 1;");
        __syncthreads();

        if (it + 2 < DMODEL / 32)
            load_stage((it + 2) % 3, (it + 2) * 32);
        asm volatile("cp.async.commit_group;");

#pragma unroll
        for (int ks = 0; ks < 2; ks++) {
            const int kw = ks * 8;
            unsigned af[4][4], bf[4][2];
#pragma unroll
            for (int mt = 0; mt < 4; mt++)
                ldsm4(af[mt], saddr(&As[cur][wm * 64 + mt * 16 + arow][kw + acol4]));
#pragma unroll
            for (int nt = 0; nt < 4; nt++)
                ldsm2(bf[nt], saddr(&Bs[cur][wn * 32 + nt * 8 + brow][kw + bcol4]));
#pragma unroll
            for (int mt = 0; mt < 4; mt++)
#pragma unroll
                for (int nt = 0; nt < 4; nt++)
                    mma16(acc[mt][nt], af[mt], bf[nt]);
        }
    }

#pragma unroll
    for (int nt = 0; nt < 4; nt++) {
        const int col = n0 + wn * 32 + nt * 8 + 2 * t;
        const float2 bb = *(const float2*)(bias + col);
#pragma unroll
        for (int mt = 0; mt < 4; mt++) {
            const int mlo = m0 + wm * 64 + mt * 16 + g;
            float2 o0 = {acc[mt][nt][0] + bb.x, acc[mt][nt][1] + bb.y};
            float2 o1 = {acc[mt][nt][2] + bb.x, acc[mt][nt][3] + bb.y};
            *(float2*)(C + (size_t)mlo * DMODEL + col) = o0;
            *(float2*)(C + (size_t)(mlo + 8) * DMODEL + col) = o1;
        }
    }
}

// ---------------------------------------------------------------------------
// Scores + exp: p_u = exp(qk/8 + mask - 4) (fp16) + row-sum partials.
// P tile staged in smem (aliasing dead Q/K tiles), coalesced copy-out.
// ---------------------------------------------------------------------------
__global__ __launch_bounds__(256, 2) void scores_exp_kernel(const float* __restrict__ mask)
{
    __shared__ unsigned Tile[2][128][36];
    __shared__ float redL[4][128];

    unsigned (*As)[36] = Tile[0];
    unsigned (*Bs)[36] = Tile[1];
    unsigned* Pst = &Tile[0][0][0];

    const int tid = threadIdx.x;
    const int bh = blockIdx.z;
    const int b = bh >> 4;
    const int sq0 = blockIdx.y * 128;
    const int st0 = blockIdx.x * 128;
    const int lane = tid & 31;
    const int warp = tid >> 5;
    const int g = lane >> 2;
    const int t = lane & 3;
    const int wm = warp >> 2;
    const int wn = warp & 3;
    const int arow = ((lane >> 3) & 1) * 8 + (lane & 7);
    const int acol4 = (lane >> 4) * 4;
    const int brow = lane & 7;
    const int bcol4 = ((lane >> 3) & 1) * 4;

    const __half* Qh = g_Qh + (size_t)bh * S_LEN * DHEAD;
    const __half* Kh = g_Kh + (size_t)bh * S_LEN * DHEAD;

#pragma unroll
    for (int i = 0; i < 4; i++) {
        const int idx = tid + 256 * i;
        const int r = idx >> 3;
        const int c = idx & 7;
        *(uint4*)&As[r][c * 4] = *(const uint4*)(Qh + (size_t)(sq0 + r) * DHEAD + c * 8);
        *(uint4*)&Bs[r][c * 4] = *(const uint4*)(Kh + (size_t)(st0 + r) * DHEAD + c * 8);
    }
    __syncthreads();

    float acc[4][4][4] = {};
#pragma unroll
    for (int ks = 0; ks < 4; ks++) {
        const int kw = ks * 8;
        unsigned af[4][4], bf[4][2];
#pragma unroll
        for (int mt = 0; mt < 4; mt++)
            ldsm4(af[mt], saddr(&As[wm * 64 + mt * 16 + arow][kw + acol4]));
#pragma unroll
        for (int nt = 0; nt < 4; nt++)
            ldsm2(bf[nt], saddr(&Bs[wn * 32 + nt * 8 + brow][kw + bcol4]));
#pragma unroll
        for (int mt = 0; mt < 4; mt++)
#pragma unroll
            for (int nt = 0; nt < 4; nt++)
                mma16(acc[mt][nt], af[mt], bf[nt]);
    }

    __syncthreads();

    const float scale = 0.125f;
#pragma unroll
    for (int mt = 0; mt < 4; mt++) {
        const int r_lo = wm * 64 + mt * 16 + g;
        const int sq_lo = sq0 + r_lo;
        float rs0 = 0.f, rs1 = 0.f;
#pragma unroll
        for (int nt = 0; nt < 4; nt++) {
            const int cc = wn * 32 + nt * 8 + 2 * t;
            const int st = st0 + cc;
            float2 mk0 = *(const float2*)(mask + ((size_t)b * S_LEN + sq_lo) * S_LEN + st);
            float2 mk1 = *(const float2*)(mask + ((size_t)b * S_LEN + sq_lo + 8) * S_LEN + st);
            float p00 = __expf(acc[mt][nt][0] * scale + mk0.x - 4.0f);
            float p01 = __expf(acc[mt][nt][1] * scale + mk0.y - 4.0f);
            float p10 = __expf(acc[mt][nt][2] * scale + mk1.x - 4.0f);
            float p11 = __expf(acc[mt][nt][3] * scale + mk1.y - 4.0f);
            const int wcol = wn * 16 + nt * 4 + t;
            Pst[(size_t)r_lo * 68 + wcol] = pk(p00, p01);
            Pst[(size_t)(r_lo + 8) * 68 + wcol] = pk(p10, p11);
            rs0 += p00 + p01;
            rs1 += p10 + p11;
        }
        rs0 += __shfl_xor_sync(0xffffffffu, rs0, 1);
        rs0 += __shfl_xor_sync(0xffffffffu, rs0, 2);
        rs1 += __shfl_xor_sync(0xffffffffu, rs1, 1);
        rs1 += __shfl_xor_sync(0xffffffffu, rs1, 2);
        if (t == 0) {
            redL[wn][r_lo] = rs0;
            redL[wn][r_lo + 8] = rs1;
        }
    }
    __syncthreads();

#pragma unroll
    for (int i = 0; i < 8; i++) {
        const int idx = tid + 256 * i;
        const int r = idx >> 4;
        const int j = idx & 15;
        uint4 v = *(const uint4*)&Pst[(size_t)r * 68 + j * 4];
        *(uint4*)(g_Ph + ((size_t)bh * S_LEN + sq0 + r) * S_LEN + st0 + j * 8) = v;
    }

    if (tid < 128) {
        float s = redL[0][tid] + redL[1][tid] + redL[2][tid] + redL[3][tid];
        g_Lp[((size_t)bh * 16 + blockIdx.x) * S_LEN + sq0 + tid] = s;
    }
}

// ---------------------------------------------------------------------------
// Deterministic reduce of row-sum partials -> 1/l
// ---------------------------------------------------------------------------
__global__ __launch_bounds__(256) void sumL_kernel()
{
    const int idx = blockIdx.x * 256 + threadIdx.x;
    const int bh = idx >> 11;
    const int s = idx & 2047;
    float acc = 0.f;
#pragma unroll
    for (int j = 0; j < 16; j++)
        acc += g_Lp[((size_t)bh * 16 + j) * S_LEN + s];
    g_Li[idx] = 1.0f / acc;
}

// ---------------------------------------------------------------------------
// PV: Xh = (P_u @ V) * (1/l). 128x64 tile, BK=32, 4-stage cp.async pipeline.
// ---------------------------------------------------------------------------
#define PV_NIT (S_LEN / 32)

__global__ __launch_bounds__(256, 2) void pv_kernel()
{
    __shared__ unsigned Ps[4][128][20];
    __shared__ unsigned Vs[4][64][20];

    const int tid = threadIdx.x;
    const int bh = blockIdx.y;
    const int b = bh >> 4;
    const int h = bh & 15;
    const int m0 = blockIdx.x * 128;
    const int lane = tid & 31;
    const int warp = tid >> 5;
    const int g = lane >> 2;
    const int t = lane & 3;
    const int wm = warp >> 1;
    const int wn = warp & 1;
    const int arow = ((lane >> 3) & 1) * 8 + (lane & 7);
    const int acol4 = (lane >> 4) * 4;
    const int brow = lane & 7;
    const int bcol4 = ((lane >> 3) & 1) * 4;

    const __half* Ph = g_Ph + (size_t)bh * S_LEN * S_LEN;
    const __half* Vt = g_Vt + (size_t)bh * DHEAD * S_LEN;

    const int pr0 = tid >> 2;
    const int pr1 = (tid + 256) >> 2;
    const int pc = (tid & 3) * 8;
    const int vr = tid >> 2;

    auto load_stage = [&](int stage, int k) {
        cp_async16(saddr(&Ps[stage][pr0][(tid & 3) * 4]),
                   Ph + (size_t)(m0 + pr0) * S_LEN + k + pc);
        cp_async16(saddr(&Ps[stage][pr1][(tid & 3) * 4]),
                   Ph + (size_t)(m0 + pr1) * S_LEN + k + pc);
        cp_async16(saddr(&Vs[stage][vr][(tid & 3) * 4]),
                   Vt + (size_t)vr * S_LEN + k + pc);
    };

#pragma unroll
    for (int s = 0; s < 3; s++) {
        load_stage(s, s * 32);
        asm volatile("cp.async.commit_group;");
    }

    float acc[2][4][4] = {};

    for (int it = 0; it < PV_NIT; it++) {
        const int cur = it & 3;
        asm volatile("cp.async.wait_group 2;");
        __syncthreads();

        if (it + 3 < PV_NIT)
            load_stage((it + 3) & 3, (it + 3) * 32);
        asm volatile("cp.async.commit_group;");

#pragma unroll
        for (int ks = 0; ks < 2; ks++) {
            const int kw = ks * 8;
            unsigned af[2][4], bf[4][2];
#pragma unroll
            for (int mt = 0; mt < 2; mt++)
                ldsm4(af[mt], saddr(&Ps[cur][wm * 32 + mt * 16 + arow][kw + acol4]));
#pragma unroll
            for (int nt = 0; nt < 4; nt++)
                ldsm2(bf[nt], saddr(&Vs[cur][wn * 32 + nt * 8 + brow][kw + bcol4]));
#pragma unroll
            for (int mt = 0; mt < 2; mt++)
#pragma unroll
                for (int nt = 0; nt < 4; nt++)
                    mma16(acc[mt][nt], af[mt], bf[nt]);
        }
    }

#pragma unroll
    for (int mt = 0; mt < 2; mt++) {
        const int mlo = m0 + wm * 32 + mt * 16 + g;
        const float inv0 = g_Li[(size_t)bh * S_LEN + mlo];
        const float inv1 = g_Li[(size_t)bh * S_LEN + mlo + 8];
#pragma unroll
        for (int nt = 0; nt < 4; nt++) {
            const int col = wn * 32 + nt * 8 + 2 * t;
            *(__half2*)(g_Xh + ((size_t)(mlo * BATCH + b)) * DMODEL + h * DHEAD + col) =
                __floats2half2_rn(acc[mt][nt][0] * inv0, acc[mt][nt][1] * inv0);
            *(__half2*)(g_Xh + ((size_t)((mlo + 8) * BATCH + b)) * DMODEL + h * DHEAD + col) =
                __floats2half2_rn(acc[mt][nt][2] * inv1, acc[mt][nt][3] * inv1);
        }
    }
}

// ---------------------------------------------------------------------------
// attn[b][s][t] = sum_h p_u * (1/l) / 16
// ---------------------------------------------------------------------------
__global__ __launch_bounds__(256) void mean_kernel(float* __restrict__ attn)
{
    const int s = blockIdx.x;
    const int b = blockIdx.y;
    const int tid = threadIdx.x;

    float acc[8] = {};
#pragma unroll
    for (int h = 0; h < NHEAD; h++) {
        const int bh = b * NHEAD + h;
        const float inv = g_Li[(size_t)bh * S_LEN + s];
        uint4 u = *(const uint4*)(g_Ph + ((size_t)bh * S_LEN + s) * S_LEN + tid * 8);
        const __half2* hp = (const __half2*)&u;
#pragma unroll
        for (int j = 0; j < 4; j++) {
            float2 f = __half22float2(hp[j]);
            acc[2 * j] += f.x * inv;
            acc[2 * j + 1] += f.y * inv;
        }
    }
    const float im = 1.0f / NHEAD;
    float4 o0 = {acc[0] * im, acc[1] * im, acc[2] * im, acc[3] * im};
    float4 o1 = {acc[4] * im, acc[5] * im, acc[6] * im, acc[7] * im};
    float* dst = attn + ((size_t)b * S_LEN + s) * S_LEN + tid * 8;
    *(float4*)dst = o0;
    *(float4*)(dst + 4) = o1;
}

// ---------------------------------------------------------------------------
// Launch
// ---------------------------------------------------------------------------
extern "C" void kernel_launch(void* const* d_in, const int* in_sizes, int n_in,
                              void* d_out, int out_size)
{
    (void)in_sizes; (void)n_in; (void)out_size;

    const float* query = (const float*)d_in[0];
    const float* key_in = (const float*)d_in[1];
    const float* value = (const float*)d_in[2];
    const float* mask  = (const float*)d_in[3];
    const float* Wq = (const float*)d_in[4];
    const float* bq = (const float*)d_in[5];
    const float* Wk = (const float*)d_in[6];
    const float* bk = (const float*)d_in[7];
    const float* Wv = (const float*)d_in[8];
    const float* bv = (const float*)d_in[9];
    const float* Wo = (const float*)d_in[10];
    const float* bo = (const float*)d_in[11];

    float* out  = (float*)d_out;
    float* attn = out + (size_t)S_LEN * BATCH * DMODEL;

    // prep: y 0..2 -> inputs (4M elems), y 3..6 -> weights (1M elems)
    prep_kernel<<<dim3(NIN / (256 * 8), 7), 256>>>(query, key_in, value, Wq, Wk, Wv, Wo);

    dim3 pgrid3(DMODEL / 128, NROWS / 128, 3);   // (8, 32, 3) merged QKV

    proj_qkv_kernel<<<pgrid3, 256>>>(bq, bk, bv);

    scores_exp_kernel<<<dim3(S_LEN / 128, S_LEN / 128, BH), 256>>>(mask);

    sumL_kernel<<<(BH * S_LEN) / 256, 256>>>();

    pv_kernel<<<dim3(S_LEN / 128, BH), 256>>>();

    mean_kernel<<<dim3(S_LEN, BATCH), 256>>>(attn);

    proj_o_kernel<<<dim3(DMODEL / 128, NROWS / 128), 256>>>(bo, out);
}